// round 13
// baseline (speedup 1.0000x reference)
#include <cuda_runtime.h>
#include <cuda_bf16.h>
#include <math.h>
#include <stdint.h>

#define Nn 10000
#define Ee 320000
#define Hh 128
#define EPSf 1e-8f
#define NT64 5000
#define EDGE_GRID 148
#define EDGE_THREADS 512
#define NODE_PER_BLK 68
#define NODE_ROWS 80

// ---------------- scratch ----------------------------------------------------
__device__ float g_temb[Hh];
__device__ float g_hfeat[2][Nn * Hh];
__device__ float g_x[2][Nn * 3];
__device__ float g_P[Nn * Hh];
__device__ float g_Q[Nn * Hh];
__device__ float g_CW[16 * Hh];
__device__ float g_b1eff[Hh];
__device__ float g_aggmsg[Nn * Hh];
__device__ float g_aggtrans[Nn * 3];
__device__ int g_bar_cnt = 0;
__device__ int g_bar_flag = 0;

__device__ __forceinline__ float siluf(float x) { return x / (1.0f + __expf(-x)); }

__device__ __forceinline__ void mma16(float* d, const uint32_t* a, uint32_t b0, uint32_t b1) {
    asm volatile("mma.sync.aligned.m16n8k16.row.col.f32.bf16.bf16.f32 "
        "{%0,%1,%2,%3}, {%4,%5,%6,%7}, {%8,%9}, {%0,%1,%2,%3};"
        : "+f"(d[0]), "+f"(d[1]), "+f"(d[2]), "+f"(d[3])
        : "r"(a[0]), "r"(a[1]), "r"(a[2]), "r"(a[3]), "r"(b0), "r"(b1));
}

__device__ __forceinline__ void ldm4(uint32_t* r, uint32_t addr) {
    asm volatile("ldmatrix.sync.aligned.m8n8.x4.shared.b16 {%0,%1,%2,%3}, [%4];"
        : "=r"(r[0]), "=r"(r[1]), "=r"(r[2]), "=r"(r[3]) : "r"(addr));
}

__device__ __forceinline__ uint32_t smem_u32(const void* p) {
    uint32_t a;
    asm("{ .reg .u64 t; cvta.to.shared.u64 t, %1; cvt.u32.u64 %0, t; }" : "=r"(a) : "l"(p));
    return a;
}

__device__ __forceinline__ void split2(float x0, float x1, uint32_t& hi, uint32_t& lo) {
    __nv_bfloat162 h = __floats2bfloat162_rn(x0, x1);
    float h0 = __bfloat162float(__low2bfloat16(h));
    float h1 = __bfloat162float(__high2bfloat16(h));
    __nv_bfloat162 l = __floats2bfloat162_rn(x0 - h0, x1 - h1);
    hi = *(uint32_t*)&h;
    lo = *(uint32_t*)&l;
}

__device__ __forceinline__ void bar_sync(int id, int cnt) {
    asm volatile("bar.sync %0, %1;" :: "r"(id), "r"(cnt) : "memory");
}

// sense-reversing device-wide barrier (all CTAs resident)
__device__ __forceinline__ void global_bar(int* sense) {
    __syncthreads();
    if (threadIdx.x == 0) {
        int s = *sense;
        __threadfence();
        int v = atomicAdd(&g_bar_cnt, 1);
        if (v == (int)gridDim.x - 1) {
            g_bar_cnt = 0;
            __threadfence();
            *(volatile int*)&g_bar_flag = 1 - s;
        } else {
            while (*(volatile int*)&g_bar_flag == s) __nanosleep(64);
        }
    }
    __syncthreads();
    *sense = 1 - *sense;
    __threadfence();
}

// ================= init = temb | zero agg ====================================
#define NB_AGG 5118
__global__ void __launch_bounds__(256, 1) init_kernel(
    const float* __restrict__ t,
    const float* __restrict__ w1, const float* __restrict__ b1,
    const float* __restrict__ w2, const float* __restrict__ b2) {
    int b = blockIdx.x, tid = threadIdx.x;
    if (b == 0) {
        __shared__ float sh[Hh];
        float tv = t[0];
        if (tid < Hh) sh[tid] = siluf(tv * w1[tid] + b1[tid]);
        __syncthreads();
        if (tid < Hh) {
            float acc = b2[tid];
            #pragma unroll 4
            for (int k = 0; k < Hh; k++) acc = fmaf(sh[k], w2[k * Hh + tid], acc);
            g_temb[tid] = acc;
        }
    } else {
        int i = (b - 1) * 256 + tid;
        if (i < Nn * Hh) g_aggmsg[i] = 0.f;
        else if (i < Nn * Hh + Nn * 3) g_aggtrans[i - Nn * Hh] = 0.f;
    }
}

// ====== emb: hfeat(h@W+b+temb) | copyx =======================================
#define NB_HF 157
#define NB_CX 118
__global__ void __launch_bounds__(256, 1) emb_kernel(
    const float* __restrict__ h, const float* __restrict__ W, const float* __restrict__ B,
    const float* __restrict__ x) {
    int b = blockIdx.x, tid = threadIdx.x;
    if (b < NB_HF) {
        extern __shared__ float sIn[];
        int n0 = b * 64;
        for (int idx = tid; idx < 64 * 64; idx += 256) {
            int i = idx >> 6, k = idx & 63;
            int node = n0 + i;
            sIn[idx] = (node < Nn) ? h[node * 64 + k] : 0.f;
        }
        __syncthreads();
        int jc = tid & 31, wp = tid >> 5;
        float acc[8][4];
        #pragma unroll
        for (int r = 0; r < 8; r++) { acc[r][0]=acc[r][1]=acc[r][2]=acc[r][3]=0.f; }
        const float4* Wv = (const float4*)W;
        for (int k = 0; k < 64; k++) {
            float4 w = Wv[k * 32 + jc];
            #pragma unroll
            for (int r = 0; r < 8; r++) {
                float a = sIn[(wp * 8 + r) * 64 + k];
                acc[r][0]=fmaf(a,w.x,acc[r][0]); acc[r][1]=fmaf(a,w.y,acc[r][1]);
                acc[r][2]=fmaf(a,w.z,acc[r][2]); acc[r][3]=fmaf(a,w.w,acc[r][3]);
            }
        }
        float4 bv = ((const float4*)B)[jc];
        float4 tv = ((const float4*)g_temb)[jc];
        #pragma unroll
        for (int r = 0; r < 8; r++) {
            int node = n0 + wp * 8 + r;
            if (node < Nn) {
                float4 o;
                o.x = acc[r][0]+bv.x+tv.x; o.y = acc[r][1]+bv.y+tv.y;
                o.z = acc[r][2]+bv.z+tv.z; o.w = acc[r][3]+bv.w+tv.w;
                ((float4*)(g_hfeat[0] + node * Hh))[jc] = o;
            }
        }
    } else {
        int i = (b - NB_HF) * 256 + tid;
        if (i < Nn * 3) g_x[0][i] = x[i];
    }
}

// ---------------- layer-0 prep roles -----------------------------------------
__device__ void setup_role256(const float* __restrict__ eew, const float* __restrict__ eeb,
                              const float* __restrict__ W1, const float* __restrict__ B1) {
    int tid = threadIdx.x;
    for (int o = tid; o < 16 * Hh; o += 256) {
        int i = o >> 7, j = o & 127;
        float acc = 0.f;
        #pragma unroll 4
        for (int k = 0; k < Hh; k++)
            acc = fmaf(eew[i * Hh + k], W1[(257 + k) * Hh + j], acc);
        g_CW[o] = acc;
    }
    if (tid < Hh) {
        float acc = B1[tid];
        #pragma unroll 4
        for (int k = 0; k < Hh; k++)
            acc = fmaf(eeb[k], W1[(257 + k) * Hh + tid], acc);
        g_b1eff[tid] = acc;
    }
}

__device__ void pq_role(const float* __restrict__ W1, int sel, int blk) {
    extern __shared__ float sIn[];
    const float* hc = g_hfeat[sel];
    int tid = threadIdx.x;
    int n0 = blk * 64;
    for (int idx = tid; idx < 64 * Hh; idx += 256) {
        int i = idx >> 7, k = idx & 127;
        int node = n0 + i;
        sIn[idx] = (node < Nn) ? hc[node * Hh + k] : 0.f;
    }
    __syncthreads();
    int jc = tid & 31, wp = tid >> 5;
    #pragma unroll
    for (int pass = 0; pass < 2; pass++) {
        const float4* Wv = (const float4*)(W1 + (size_t)pass * 128 * Hh);
        float* dst = pass ? g_Q : g_P;
        float acc[8][4];
        #pragma unroll
        for (int r = 0; r < 8; r++) { acc[r][0]=acc[r][1]=acc[r][2]=acc[r][3]=0.f; }
        for (int k = 0; k < Hh; k++) {
            float4 w = Wv[k * 32 + jc];
            #pragma unroll
            for (int r = 0; r < 8; r++) {
                float a = sIn[(wp * 8 + r) * Hh + k];
                acc[r][0]=fmaf(a,w.x,acc[r][0]); acc[r][1]=fmaf(a,w.y,acc[r][1]);
                acc[r][2]=fmaf(a,w.z,acc[r][2]); acc[r][3]=fmaf(a,w.w,acc[r][3]);
            }
        }
        #pragma unroll
        for (int r = 0; r < 8; r++) {
            int node = n0 + wp * 8 + r;
            if (node < Nn) {
                float4 o; o.x=acc[r][0]; o.y=acc[r][1]; o.z=acc[r][2]; o.w=acc[r][3];
                ((float4*)(dst + node * Hh))[jc] = o;
            }
        }
    }
}

__global__ void __launch_bounds__(256, 1) prep_kernel(
    const float* __restrict__ eew, const float* __restrict__ eeb,
    const float* __restrict__ W1, const float* __restrict__ B1, int sel) {
    int b = blockIdx.x;
    if (b == 0) setup_role256(eew, eeb, W1, B1);
    else pq_role(W1, sel, b - 1);
}

// ================= persistent 4-layer mega kernel ============================
#define O_W2H  0
#define O_W2L  8704
#define O_C1H  17408
#define O_C1L  26112
#define O_A    34816
#define O_EA   52224
#define O_CW   54272
#define O_WD   56320
#define O_B1   56448
#define O_B2   56576
#define O_CB   56704
#define O_C2   56832
#define O_GEO  56960
#define SMEM_EDGE_WORDS 57984

__global__ void __launch_bounds__(EDGE_THREADS, 1) mega_kernel(
    const int* __restrict__ rowi, const int* __restrict__ coli,
    const float* __restrict__ ea, const float* __restrict__ mask,
    const float* __restrict__ x_in, float* __restrict__ out,
    const float* __restrict__ ew1, const float* __restrict__ eb1,
    const float* __restrict__ ew2, const float* __restrict__ eb2,
    const float* __restrict__ cw1, const float* __restrict__ cb1,
    const float* __restrict__ cw2,
    const float* __restrict__ nw1, const float* __restrict__ nb1,
    const float* __restrict__ nw2, const float* __restrict__ nb2,
    const float* __restrict__ eew, const float* __restrict__ eeb) {
    extern __shared__ float F[];
    uint32_t* U = (uint32_t*)F;
    int tid = threadIdx.x;
    int lane = tid & 31, w = tid >> 5;
    int sense = 0;

    // edge decomposition constants
    int grp = w >> 3;
    int gw = w & 7;
    int gtid = tid & 255;
    int barid = 1 + grp;
    int mi = gw & 1, ni = gw >> 1;
    int g = lane >> 2, tg = lane & 3;

    uint32_t* sW2H = U + O_W2H;
    uint32_t* sW2L = U + O_W2L;
    uint32_t* sC1H = U + O_C1H;
    uint32_t* sC1L = U + O_C1L;
    float* sCW = F + O_CW;
    float* sWd = F + O_WD;
    float* sB1 = F + O_B1;
    float* sB2 = F + O_B2;
    float* sCB = F + O_CB;
    float* sC2 = F + O_C2;
    uint32_t* AH = U + O_A + grp * 8704;
    uint32_t* AL = AH + 4352;
    float* sEA  = F + O_EA + grp * 1024;
    float* GEO  = F + O_GEO + grp * 512;
    int*   sRow = (int*)GEO;
    int*   sCol = (int*)(GEO + 64);
    float* sD2v = GEO + 128;
    float* sDist= GEO + 192;
    float* sPart= GEO + 256;
    float* sDiff= GEO + 320;

    uint32_t uAH = smem_u32(AH), uAL = smem_u32(AL);
    uint32_t uW2H = smem_u32(sW2H), uW2L = smem_u32(sW2L);
    uint32_t uC1H = smem_u32(sC1H), uC1L = smem_u32(sC1L);
    int l15 = lane & 15;
    uint32_t aoff0 = (uint32_t)(((mi * 32 + l15) * 68 + (lane >> 4) * 4) * 4);
    uint32_t aoff1 = aoff0 + 16 * 68 * 4;
    int bj = (lane >> 4) & 1, bg = (lane >> 3) & 1, b8 = lane & 7;
    uint32_t boff0 = (uint32_t)(((ni * 32 + bj * 8 + b8) * 68 + bg * 4) * 4);
    uint32_t boff1 = boff0 + 16 * 68 * 4;

    // node-phase smem (overlays edge region between phases)
    float* nIn = F;               // 80 x 256
    float* nH  = F + 80 * 256;    // 80 x 128

    for (int l = 0; l < 4; l++) {
        int sel = l & 1;
        const float* W1  = ew1 + (size_t)l * 385 * Hh;
        const float* W2g = ew2 + (size_t)l * Hh * Hh;
        const float* B2  = eb2 + l * Hh;
        const float* C1g = cw1 + (size_t)l * Hh * Hh;
        const float* CB  = cb1 + l * Hh;
        const float* C2  = cw2 + (size_t)l * Hh;
        const float* xc  = g_x[sel];

        // ========== EDGE PHASE ==========
        for (int idx = tid; idx < 64 * 128; idx += EDGE_THREADS) {
            int kp = idx >> 7, n = idx & 127;
            uint32_t hi, lo;
            split2(W2g[(2 * kp) * 128 + n], W2g[(2 * kp + 1) * 128 + n], hi, lo);
            sW2H[n * 68 + kp] = hi;
            sW2L[n * 68 + kp] = lo;
            split2(C1g[(2 * kp) * 128 + n], C1g[(2 * kp + 1) * 128 + n], hi, lo);
            sC1H[n * 68 + kp] = hi;
            sC1L[n * 68 + kp] = lo;
        }
        for (int idx = tid; idx < 16 * Hh; idx += EDGE_THREADS) sCW[idx] = g_CW[idx];
        if (tid < Hh) {
            sWd[tid] = W1[256 * Hh + tid];
            sB1[tid] = g_b1eff[tid];
            sB2[tid] = B2[tid];
            sCB[tid] = CB[tid];
            sC2[tid] = C2[tid];
        }
        __syncthreads();

        int stride = gridDim.x * 2;
        int tile0 = blockIdx.x * 2 + grp;

        int pf_r = 0, pf_c = 0;
        float4 pf_ea = make_float4(0.f, 0.f, 0.f, 0.f);
        if (tile0 < NT64) {
            int e0 = tile0 * 64;
            if (gtid < 64) { pf_r = rowi[e0 + gtid]; pf_c = coli[e0 + gtid]; }
            pf_ea = ((const float4*)(ea + (size_t)(e0 + (gtid >> 2)) * 16))[gtid & 3];
        }

        for (int tile = tile0; tile < NT64; tile += stride) {
            if (gtid < 64) {
                int r = pf_r, c = pf_c;
                sRow[gtid] = r; sCol[gtid] = c;
                float dx = xc[r*3+0] - xc[c*3+0];
                float dy = xc[r*3+1] - xc[c*3+1];
                float dz = xc[r*3+2] - xc[c*3+2];
                float d2 = dx*dx + dy*dy + dz*dz;
                sDiff[gtid*3+0] = dx; sDiff[gtid*3+1] = dy; sDiff[gtid*3+2] = dz;
                sD2v[gtid] = d2;
                sDist[gtid] = sqrtf(d2 + EPSf);
                sPart[gtid] = 0.f;
            }
            {
                int e = gtid >> 2, q = gtid & 3;
                float* dst = sEA + e * 16 + q * 4;
                dst[0] = pf_ea.x; dst[1] = pf_ea.y; dst[2] = pf_ea.z; dst[3] = pf_ea.w;
            }
            bar_sync(barid, 256);

            {
                int tn = tile + stride;
                if (tn < NT64) {
                    int e0n = tn * 64;
                    if (gtid < 64) { pf_r = rowi[e0n + gtid]; pf_c = coli[e0n + gtid]; }
                    pf_ea = ((const float4*)(ea + (size_t)(e0n + (gtid >> 2)) * 16))[gtid & 3];
                }
            }

            {
                int jc = lane;
                float acc[8][4];
                float4 wd = ((const float4*)sWd)[jc];
                float4 b1 = ((const float4*)sB1)[jc];
                #pragma unroll
                for (int r = 0; r < 8; r++) {
                    int e = gw * 8 + r;
                    int rw = sRow[e], cl = sCol[e];
                    float d2 = sD2v[e];
                    float4 pp = ((const float4*)(g_P + (size_t)rw * Hh))[jc];
                    float4 qq = ((const float4*)(g_Q + (size_t)cl * Hh))[jc];
                    acc[r][0] = pp.x + qq.x + fmaf(d2, wd.x, b1.x);
                    acc[r][1] = pp.y + qq.y + fmaf(d2, wd.y, b1.y);
                    acc[r][2] = pp.z + qq.z + fmaf(d2, wd.z, b1.z);
                    acc[r][3] = pp.w + qq.w + fmaf(d2, wd.w, b1.w);
                }
                const float4* CW4 = (const float4*)sCW;
                #pragma unroll
                for (int k = 0; k < 16; k++) {
                    float4 cw = CW4[k * 32 + jc];
                    #pragma unroll
                    for (int r = 0; r < 8; r++) {
                        float a = sEA[(gw * 8 + r) * 16 + k];
                        acc[r][0] = fmaf(a, cw.x, acc[r][0]);
                        acc[r][1] = fmaf(a, cw.y, acc[r][1]);
                        acc[r][2] = fmaf(a, cw.z, acc[r][2]);
                        acc[r][3] = fmaf(a, cw.w, acc[r][3]);
                    }
                }
                #pragma unroll
                for (int r = 0; r < 8; r++) {
                    int e = gw * 8 + r;
                    float s0 = siluf(acc[r][0]), s1 = siluf(acc[r][1]);
                    float s2 = siluf(acc[r][2]), s3 = siluf(acc[r][3]);
                    uint32_t h0, l0, h1p, l1;
                    split2(s0, s1, h0, l0);
                    split2(s2, s3, h1p, l1);
                    *(uint2*)(AH + e * 68 + 2 * jc) = make_uint2(h0, h1p);
                    *(uint2*)(AL + e * 68 + 2 * jc) = make_uint2(l0, l1);
                }
            }
            bar_sync(barid, 256);

            float d[2][4][4];

            #pragma unroll
            for (int mt = 0; mt < 2; mt++)
                #pragma unroll
                for (int j = 0; j < 4; j++)
                    d[mt][j][0] = d[mt][j][1] = d[mt][j][2] = d[mt][j][3] = 0.f;
            #pragma unroll
            for (int ks = 0; ks < 8; ks++) {
                uint32_t koff = (uint32_t)(ks * 32);
                uint32_t ah0[4], ah1[4], al0[4], al1[4], bh[8], bl[8];
                ldm4(ah0, uAH + aoff0 + koff);
                ldm4(ah1, uAH + aoff1 + koff);
                ldm4(al0, uAL + aoff0 + koff);
                ldm4(al1, uAL + aoff1 + koff);
                ldm4(bh,     uW2H + boff0 + koff);
                ldm4(bh + 4, uW2H + boff1 + koff);
                ldm4(bl,     uW2L + boff0 + koff);
                ldm4(bl + 4, uW2L + boff1 + koff);
                #pragma unroll
                for (int j = 0; j < 4; j++) {
                    uint32_t b0h = bh[j*2], b1h = bh[j*2+1];
                    uint32_t b0l = bl[j*2], b1l = bl[j*2+1];
                    mma16(d[0][j], ah0, b0h, b1h);
                    mma16(d[1][j], ah1, b0h, b1h);
                    mma16(d[0][j], ah0, b0l, b1l);
                    mma16(d[1][j], ah1, b0l, b1l);
                    mma16(d[0][j], al0, b0h, b1h);
                    mma16(d[1][j], al1, b0h, b1h);
                }
            }
            bar_sync(barid, 256);

            #pragma unroll
            for (int mt = 0; mt < 2; mt++) {
                int er0 = mi * 32 + mt * 16 + g;
                int er1 = er0 + 8;
                int rw0 = sRow[er0], rw1 = sRow[er1];
                #pragma unroll
                for (int j = 0; j < 4; j++) {
                    int c = ni * 32 + j * 8 + 2 * tg;
                    float m00 = siluf(d[mt][j][0] + sB2[c]);
                    float m01 = siluf(d[mt][j][1] + sB2[c + 1]);
                    float m10 = siluf(d[mt][j][2] + sB2[c]);
                    float m11 = siluf(d[mt][j][3] + sB2[c + 1]);
                    asm volatile("red.global.add.v2.f32 [%0], {%1,%2};"
                                 :: "l"(g_aggmsg + (size_t)rw0 * Hh + c), "f"(m00), "f"(m01) : "memory");
                    asm volatile("red.global.add.v2.f32 [%0], {%1,%2};"
                                 :: "l"(g_aggmsg + (size_t)rw1 * Hh + c), "f"(m10), "f"(m11) : "memory");
                    uint32_t hi, lo;
                    split2(m00, m01, hi, lo);
                    AH[er0 * 68 + (c >> 1)] = hi;
                    AL[er0 * 68 + (c >> 1)] = lo;
                    split2(m10, m11, hi, lo);
                    AH[er1 * 68 + (c >> 1)] = hi;
                    AL[er1 * 68 + (c >> 1)] = lo;
                }
            }
            bar_sync(barid, 256);

            #pragma unroll
            for (int mt = 0; mt < 2; mt++)
                #pragma unroll
                for (int j = 0; j < 4; j++)
                    d[mt][j][0] = d[mt][j][1] = d[mt][j][2] = d[mt][j][3] = 0.f;
            #pragma unroll
            for (int ks = 0; ks < 8; ks++) {
                uint32_t koff = (uint32_t)(ks * 32);
                uint32_t ah0[4], ah1[4], al0[4], al1[4], bh[8], bl[8];
                ldm4(ah0, uAH + aoff0 + koff);
                ldm4(ah1, uAH + aoff1 + koff);
                ldm4(al0, uAL + aoff0 + koff);
                ldm4(al1, uAL + aoff1 + koff);
                ldm4(bh,     uC1H + boff0 + koff);
                ldm4(bh + 4, uC1H + boff1 + koff);
                ldm4(bl,     uC1L + boff0 + koff);
                ldm4(bl + 4, uC1L + boff1 + koff);
                #pragma unroll
                for (int j = 0; j < 4; j++) {
                    uint32_t b0h = bh[j*2], b1h = bh[j*2+1];
                    uint32_t b0l = bl[j*2], b1l = bl[j*2+1];
                    mma16(d[0][j], ah0, b0h, b1h);
                    mma16(d[1][j], ah1, b0h, b1h);
                    mma16(d[0][j], ah0, b0l, b1l);
                    mma16(d[1][j], ah1, b0l, b1l);
                    mma16(d[0][j], al0, b0h, b1h);
                    mma16(d[1][j], al1, b0h, b1h);
                }
            }

            {
                float prt[2][2];
                prt[0][0] = prt[0][1] = prt[1][0] = prt[1][1] = 0.f;
                #pragma unroll
                for (int mt = 0; mt < 2; mt++) {
                    #pragma unroll
                    for (int j = 0; j < 4; j++) {
                        int c = ni * 32 + j * 8 + 2 * tg;
                        float c2a = sC2[c], c2b = sC2[c + 1];
                        float u00 = siluf(d[mt][j][0] + sCB[c]);
                        float u01 = siluf(d[mt][j][1] + sCB[c + 1]);
                        float u10 = siluf(d[mt][j][2] + sCB[c]);
                        float u11 = siluf(d[mt][j][3] + sCB[c + 1]);
                        prt[mt][0] += u00 * c2a + u01 * c2b;
                        prt[mt][1] += u10 * c2a + u11 * c2b;
                    }
                }
                #pragma unroll
                for (int mt = 0; mt < 2; mt++) {
                    #pragma unroll
                    for (int rh = 0; rh < 2; rh++) {
                        float pv = prt[mt][rh];
                        pv += __shfl_xor_sync(0xffffffffu, pv, 1);
                        pv += __shfl_xor_sync(0xffffffffu, pv, 2);
                        if (tg == 0)
                            atomicAdd(&sPart[mi * 32 + mt * 16 + rh * 8 + g], pv);
                    }
                }
            }
            bar_sync(barid, 256);

            if (gtid < 64) {
                float wsc = tanhf(sPart[gtid]);
                float s = wsc / (sDist[gtid] + EPSf);
                int rw = sRow[gtid];
                atomicAdd(&g_aggtrans[rw * 3 + 0], sDiff[gtid * 3 + 0] * s);
                atomicAdd(&g_aggtrans[rw * 3 + 1], sDiff[gtid * 3 + 1] * s);
                atomicAdd(&g_aggtrans[rw * 3 + 2], sDiff[gtid * 3 + 2] * s);
            }
            bar_sync(barid, 256);
        }

        global_bar(&sense);

        // ========== NODE PHASE (68 nodes/CTA, 80-row padded, 16 warps x 5) ==
        {
            const float* hc = g_hfeat[sel];
            float* hn = g_hfeat[1 - sel];
            const float* N1w = nw1 + (size_t)l * 256 * Hh;
            const float* NB1 = nb1 + l * Hh;
            const float* N2w = nw2 + (size_t)l * Hh * Hh;
            const float* NB2 = nb2 + l * Hh;
            int n0 = blockIdx.x * NODE_PER_BLK;

            for (int idx = tid; idx < NODE_ROWS * Hh; idx += EDGE_THREADS) {
                int i = idx >> 7, k = idx & 127;
                int node = n0 + i;
                float hv = 0.f, av = 0.f;
                if (i < NODE_PER_BLK && node < Nn) {
                    hv = hc[node * Hh + k];
                    av = g_aggmsg[node * Hh + k];
                    g_aggmsg[node * Hh + k] = 0.f;
                }
                nIn[i * 256 + k] = hv;
                nIn[i * 256 + 128 + k] = av;
            }
            __syncthreads();

            int jc = lane, wp = w;   // 16 warps
            {
                float acc[5][4];
                #pragma unroll
                for (int r = 0; r < 5; r++) { acc[r][0]=acc[r][1]=acc[r][2]=acc[r][3]=0.f; }
                const float4* Wv = (const float4*)N1w;
                for (int k = 0; k < 256; k++) {
                    float4 wv = Wv[k * 32 + jc];
                    #pragma unroll
                    for (int r = 0; r < 5; r++) {
                        float a = nIn[(wp * 5 + r) * 256 + k];
                        acc[r][0]=fmaf(a,wv.x,acc[r][0]); acc[r][1]=fmaf(a,wv.y,acc[r][1]);
                        acc[r][2]=fmaf(a,wv.z,acc[r][2]); acc[r][3]=fmaf(a,wv.w,acc[r][3]);
                    }
                }
                float4 bv = ((const float4*)NB1)[jc];
                #pragma unroll
                for (int r = 0; r < 5; r++) {
                    float4 o;
                    o.x = siluf(acc[r][0]+bv.x); o.y = siluf(acc[r][1]+bv.y);
                    o.z = siluf(acc[r][2]+bv.z); o.w = siluf(acc[r][3]+bv.w);
                    ((float4*)nH)[(wp * 5 + r) * 32 + jc] = o;
                }
            }
            __syncthreads();
            {
                float acc[5][4];
                #pragma unroll
                for (int r = 0; r < 5; r++) { acc[r][0]=acc[r][1]=acc[r][2]=acc[r][3]=0.f; }
                const float4* Wv = (const float4*)N2w;
                for (int k = 0; k < Hh; k++) {
                    float4 wv = Wv[k * 32 + jc];
                    #pragma unroll
                    for (int r = 0; r < 5; r++) {
                        float a = nH[(wp * 5 + r) * Hh + k];
                        acc[r][0]=fmaf(a,wv.x,acc[r][0]); acc[r][1]=fmaf(a,wv.y,acc[r][1]);
                        acc[r][2]=fmaf(a,wv.z,acc[r][2]); acc[r][3]=fmaf(a,wv.w,acc[r][3]);
                    }
                }
                float4 bv = ((const float4*)NB2)[jc];
                __syncthreads();   // nIn 256-wide reads done; reuse as 128-wide h_new
                #pragma unroll
                for (int r = 0; r < 5; r++) {
                    int row = wp * 5 + r;
                    int node = n0 + row;
                    float4 o = make_float4(0.f, 0.f, 0.f, 0.f);
                    if (row < NODE_PER_BLK && node < Nn) {
                        float4 hv = ((const float4*)(hc + node * Hh))[jc];
                        o.x = hv.x + acc[r][0] + bv.x; o.y = hv.y + acc[r][1] + bv.y;
                        o.z = hv.z + acc[r][2] + bv.z; o.w = hv.w + acc[r][3] + bv.w;
                        ((float4*)(hn + node * Hh))[jc] = o;
                    }
                    ((float4*)nIn)[row * 32 + jc] = o;
                }
            }
            if (tid < NODE_PER_BLK) {
                int node = n0 + tid;
                if (node < Nn) {
                    float mk = mask[node];
                    const float* xr = g_x[sel];
                    float* xw = g_x[1 - sel];
                    float ax = g_aggtrans[node*3+0];
                    float ay = g_aggtrans[node*3+1];
                    float az = g_aggtrans[node*3+2];
                    float nx = xr[node*3+0] + ax * mk;
                    float ny = xr[node*3+1] + ay * mk;
                    float nz = xr[node*3+2] + az * mk;
                    xw[node*3+0] = nx;
                    xw[node*3+1] = ny;
                    xw[node*3+2] = nz;
                    g_aggtrans[node*3+0] = 0.f;
                    g_aggtrans[node*3+1] = 0.f;
                    g_aggtrans[node*3+2] = 0.f;
                    if (l == 3) {
                        out[node*3+0] = (nx - x_in[node*3+0]) * mk;
                        out[node*3+1] = (ny - x_in[node*3+1]) * mk;
                        out[node*3+2] = (nz - x_in[node*3+2]) * mk;
                    }
                }
            }

            if (l < 3) {
                const float* W1n = ew1 + (size_t)(l + 1) * 385 * Hh;
                __syncthreads();
                #pragma unroll
                for (int pass = 0; pass < 2; pass++) {
                    const float4* Wv = (const float4*)(W1n + (size_t)pass * 128 * Hh);
                    float* dst = pass ? g_Q : g_P;
                    float acc[5][4];
                    #pragma unroll
                    for (int r = 0; r < 5; r++) { acc[r][0]=acc[r][1]=acc[r][2]=acc[r][3]=0.f; }
                    for (int k = 0; k < Hh; k++) {
                        float4 wv = Wv[k * 32 + jc];
                        #pragma unroll
                        for (int r = 0; r < 5; r++) {
                            float a = nIn[(wp * 5 + r) * Hh + k];
                            acc[r][0]=fmaf(a,wv.x,acc[r][0]); acc[r][1]=fmaf(a,wv.y,acc[r][1]);
                            acc[r][2]=fmaf(a,wv.z,acc[r][2]); acc[r][3]=fmaf(a,wv.w,acc[r][3]);
                        }
                    }
                    #pragma unroll
                    for (int r = 0; r < 5; r++) {
                        int row = wp * 5 + r;
                        int node = n0 + row;
                        if (row < NODE_PER_BLK && node < Nn) {
                            float4 o; o.x=acc[r][0]; o.y=acc[r][1]; o.z=acc[r][2]; o.w=acc[r][3];
                            ((float4*)(dst + node * Hh))[jc] = o;
                        }
                    }
                }
                // setup for next layer (CTA 0)
                if (blockIdx.x == 0) {
                    const float* B1n = eb1 + (l + 1) * Hh;
                    for (int o = tid; o < 16 * Hh; o += EDGE_THREADS) {
                        int i = o >> 7, j = o & 127;
                        float acc = 0.f;
                        #pragma unroll 4
                        for (int k = 0; k < Hh; k++)
                            acc = fmaf(eew[i * Hh + k], W1n[(257 + k) * Hh + j], acc);
                        g_CW[o] = acc;
                    }
                    if (tid < Hh) {
                        float acc = B1n[tid];
                        #pragma unroll 4
                        for (int k = 0; k < Hh; k++)
                            acc = fmaf(eeb[k], W1n[(257 + k) * Hh + tid], acc);
                        g_b1eff[tid] = acc;
                    }
                }
            }
        }

        global_bar(&sense);
    }
}

// ---------------- launcher ----------------------------------------------------
extern "C" void kernel_launch(void* const* d_in, const int* in_sizes, int n_in,
                              void* d_out, int out_size) {
    const float* h          = (const float*)d_in[0];
    const float* x          = (const float*)d_in[1];
    const int*   edge_index = (const int*)  d_in[2];
    const float* edge_attr  = (const float*)d_in[3];
    const float* t          = (const float*)d_in[4];
    const float* mask       = (const float*)d_in[5];
    const float* time_w1    = (const float*)d_in[6];
    const float* time_b1    = (const float*)d_in[7];
    const float* time_w2    = (const float*)d_in[8];
    const float* time_b2    = (const float*)d_in[9];
    const float* node_emb_w = (const float*)d_in[10];
    const float* node_emb_b = (const float*)d_in[11];
    const float* edge_emb_w = (const float*)d_in[12];
    const float* edge_emb_b = (const float*)d_in[13];
    const float* ew1 = (const float*)d_in[14];
    const float* eb1 = (const float*)d_in[15];
    const float* ew2 = (const float*)d_in[16];
    const float* eb2 = (const float*)d_in[17];
    const float* cw1 = (const float*)d_in[18];
    const float* cb1 = (const float*)d_in[19];
    const float* cw2 = (const float*)d_in[20];
    const float* nw1 = (const float*)d_in[21];
    const float* nb1 = (const float*)d_in[22];
    const float* nw2 = (const float*)d_in[23];
    const float* nb2 = (const float*)d_in[24];
    float* out = (float*)d_out;

    const int* rowi = edge_index;
    const int* coli = edge_index + Ee;

    const int SMEM_EDGE = SMEM_EDGE_WORDS * 4;   // 231936
    const int SMEM_PQ   = 64 * Hh * 4;
    const int SMEM_HF   = 64 * 64 * 4;

    cudaFuncSetAttribute(mega_kernel, cudaFuncAttributeMaxDynamicSharedMemorySize, SMEM_EDGE);

    init_kernel<<<1 + NB_AGG, 256>>>(t, time_w1, time_b1, time_w2, time_b2);
    emb_kernel<<<NB_HF + NB_CX, 256, SMEM_HF>>>(h, node_emb_w, node_emb_b, x);
    prep_kernel<<<1 + 157, 256, SMEM_PQ>>>(edge_emb_w, edge_emb_b, ew1, eb1, 0);
    mega_kernel<<<EDGE_GRID, EDGE_THREADS, SMEM_EDGE>>>(
        rowi, coli, edge_attr, mask, x, out,
        ew1, eb1, ew2, eb2, cw1, cb1, cw2,
        nw1, nb1, nw2, nb2, edge_emb_w, edge_emb_b);
}

// round 14
// speedup vs baseline: 1.0140x; 1.0140x over previous
#include <cuda_runtime.h>
#include <cuda_bf16.h>
#include <math.h>
#include <stdint.h>

#define Nn 10000
#define Ee 320000
#define Hh 128
#define EPSf 1e-8f
#define NT64 5000
#define EDGE_GRID 148
#define EDGE_THREADS 512
#define NPQT 157           // 64-node pq tiles

// ---------------- scratch ----------------------------------------------------
__device__ float g_temb[Hh];
__device__ float g_hfeat[2][Nn * Hh];
__device__ float g_x[2][Nn * 3];
__device__ float g_P[Nn * Hh];
__device__ float g_Q[Nn * Hh];
__device__ float g_CW[4 * 16 * Hh];
__device__ float g_b1eff[4 * Hh];
__device__ float g_aggmsg[Nn * Hh];
__device__ float g_aggtrans[Nn * 3];
__device__ int g_bar_cnt = 0;
__device__ volatile int g_bar_epoch = 0;

__device__ __forceinline__ float siluf(float x) { return x / (1.0f + __expf(-x)); }

__device__ __forceinline__ void mma16(float* d, const uint32_t* a, uint32_t b0, uint32_t b1) {
    asm volatile("mma.sync.aligned.m16n8k16.row.col.f32.bf16.bf16.f32 "
        "{%0,%1,%2,%3}, {%4,%5,%6,%7}, {%8,%9}, {%0,%1,%2,%3};"
        : "+f"(d[0]), "+f"(d[1]), "+f"(d[2]), "+f"(d[3])
        : "r"(a[0]), "r"(a[1]), "r"(a[2]), "r"(a[3]), "r"(b0), "r"(b1));
}

__device__ __forceinline__ void ldm4(uint32_t* r, uint32_t addr) {
    asm volatile("ldmatrix.sync.aligned.m8n8.x4.shared.b16 {%0,%1,%2,%3}, [%4];"
        : "=r"(r[0]), "=r"(r[1]), "=r"(r[2]), "=r"(r[3]) : "r"(addr));
}

__device__ __forceinline__ uint32_t smem_u32(const void* p) {
    uint32_t a;
    asm("{ .reg .u64 t; cvta.to.shared.u64 t, %1; cvt.u32.u64 %0, t; }" : "=r"(a) : "l"(p));
    return a;
}

__device__ __forceinline__ void split2(float x0, float x1, uint32_t& hi, uint32_t& lo) {
    __nv_bfloat162 h = __floats2bfloat162_rn(x0, x1);
    float h0 = __bfloat162float(__low2bfloat16(h));
    float h1 = __bfloat162float(__high2bfloat16(h));
    __nv_bfloat162 l = __floats2bfloat162_rn(x0 - h0, x1 - h1);
    hi = *(uint32_t*)&h;
    lo = *(uint32_t*)&l;
}

__device__ __forceinline__ void bar_sync(int id, int cnt) {
    asm volatile("bar.sync %0, %1;" :: "r"(id), "r"(cnt) : "memory");
}

// epoch-based device-wide barrier (all CTAs resident; barrier count per launch
// need not be even — epoch only ever increments)
__device__ __forceinline__ void global_bar() {
    __syncthreads();
    if (threadIdx.x == 0) {
        int e = g_bar_epoch;
        __threadfence();
        int v = atomicAdd(&g_bar_cnt, 1);
        if (v == (int)gridDim.x - 1) {
            g_bar_cnt = 0;
            __threadfence();
            g_bar_epoch = e + 1;
        } else {
            while (g_bar_epoch == e) __nanosleep(64);
        }
    }
    __syncthreads();
    __threadfence();
}

// ================= init = temb | zero agg | setup x4 =========================
#define NB_AGG 5118
__global__ void __launch_bounds__(256, 1) init_kernel(
    const float* __restrict__ t,
    const float* __restrict__ w1, const float* __restrict__ b1,
    const float* __restrict__ w2, const float* __restrict__ b2,
    const float* __restrict__ eew, const float* __restrict__ eeb,
    const float* __restrict__ ew1, const float* __restrict__ eb1) {
    int b = blockIdx.x, tid = threadIdx.x;
    if (b == 0) {
        __shared__ float sh[Hh];
        float tv = t[0];
        if (tid < Hh) sh[tid] = siluf(tv * w1[tid] + b1[tid]);
        __syncthreads();
        if (tid < Hh) {
            float acc = b2[tid];
            #pragma unroll 4
            for (int k = 0; k < Hh; k++) acc = fmaf(sh[k], w2[k * Hh + tid], acc);
            g_temb[tid] = acc;
        }
    } else if (b <= NB_AGG) {
        int i = (b - 1) * 256 + tid;
        if (i < Nn * Hh) g_aggmsg[i] = 0.f;
        else if (i < Nn * Hh + Nn * 3) g_aggtrans[i - Nn * Hh] = 0.f;
    } else {
        int L = b - NB_AGG - 1;   // 0..3
        const float* W1 = ew1 + (size_t)L * 385 * Hh;
        const float* B1 = eb1 + L * Hh;
        float* CW = g_CW + L * 16 * Hh;
        float* be = g_b1eff + L * Hh;
        for (int o = tid; o < 16 * Hh; o += 256) {
            int i = o >> 7, j = o & 127;
            float acc = 0.f;
            #pragma unroll 4
            for (int k = 0; k < Hh; k++)
                acc = fmaf(eew[i * Hh + k], W1[(257 + k) * Hh + j], acc);
            CW[o] = acc;
        }
        if (tid < Hh) {
            float acc = B1[tid];
            #pragma unroll 4
            for (int k = 0; k < Hh; k++)
                acc = fmaf(eeb[k], W1[(257 + k) * Hh + tid], acc);
            be[tid] = acc;
        }
    }
}

// ====== emb: hfeat(h@W+b+temb) | copyx =======================================
#define NB_HF 157
#define NB_CX 118
__global__ void __launch_bounds__(256, 1) emb_kernel(
    const float* __restrict__ h, const float* __restrict__ W, const float* __restrict__ B,
    const float* __restrict__ x) {
    int b = blockIdx.x, tid = threadIdx.x;
    if (b < NB_HF) {
        extern __shared__ float sIn[];
        int n0 = b * 64;
        for (int idx = tid; idx < 64 * 64; idx += 256) {
            int i = idx >> 6, k = idx & 63;
            int node = n0 + i;
            sIn[idx] = (node < Nn) ? h[node * 64 + k] : 0.f;
        }
        __syncthreads();
        int jc = tid & 31, wp = tid >> 5;
        float acc[8][4];
        #pragma unroll
        for (int r = 0; r < 8; r++) { acc[r][0]=acc[r][1]=acc[r][2]=acc[r][3]=0.f; }
        const float4* Wv = (const float4*)W;
        for (int k = 0; k < 64; k++) {
            float4 w = Wv[k * 32 + jc];
            #pragma unroll
            for (int r = 0; r < 8; r++) {
                float a = sIn[(wp * 8 + r) * 64 + k];
                acc[r][0]=fmaf(a,w.x,acc[r][0]); acc[r][1]=fmaf(a,w.y,acc[r][1]);
                acc[r][2]=fmaf(a,w.z,acc[r][2]); acc[r][3]=fmaf(a,w.w,acc[r][3]);
            }
        }
        float4 bv = ((const float4*)B)[jc];
        float4 tv = ((const float4*)g_temb)[jc];
        #pragma unroll
        for (int r = 0; r < 8; r++) {
            int node = n0 + wp * 8 + r;
            if (node < Nn) {
                float4 o;
                o.x = acc[r][0]+bv.x+tv.x; o.y = acc[r][1]+bv.y+tv.y;
                o.z = acc[r][2]+bv.z+tv.z; o.w = acc[r][3]+bv.w+tv.w;
                ((float4*)(g_hfeat[0] + node * Hh))[jc] = o;
            }
        }
    } else {
        int i = (b - NB_HF) * 256 + tid;
        if (i < Nn * 3) g_x[0][i] = x[i];
    }
}

// ============ edge kernel: PQ mma pre-phase + dual-pipeline edge tiles =======
#define O_W2H  0
#define O_W2L  8704
#define O_C1H  17408
#define O_C1L  26112
#define O_A    34816
#define O_EA   52224
#define O_CW   54272
#define O_WD   56320
#define O_B1   56448
#define O_B2   56576
#define O_CB   56704
#define O_C2   56832
#define O_GEO  56960
#define SMEM_EDGE_WORDS 57984

__global__ void __launch_bounds__(EDGE_THREADS, 1) edge_mma_kernel(
    const int* __restrict__ rowi, const int* __restrict__ coli,
    const float* __restrict__ ea,
    const float* __restrict__ W1,
    const float* __restrict__ W2g, const float* __restrict__ B2,
    const float* __restrict__ C1g, const float* __restrict__ CB,
    const float* __restrict__ C2, int l) {
    extern __shared__ float F[];
    uint32_t* U = (uint32_t*)F;
    uint32_t* sW2H = U + O_W2H;
    uint32_t* sW2L = U + O_W2L;
    uint32_t* sC1H = U + O_C1H;
    uint32_t* sC1L = U + O_C1L;
    float* sCW = F + O_CW;
    float* sWd = F + O_WD;
    float* sB1 = F + O_B1;
    float* sB2 = F + O_B2;
    float* sCB = F + O_CB;
    float* sC2 = F + O_C2;

    int tid = threadIdx.x;
    int lane = tid & 31, w = tid >> 5;
    int sel = l & 1;

    const float* xc = g_x[sel];
    const float* hf = g_hfeat[sel];

    int grp = w >> 3;
    int gw = w & 7;
    int gtid = tid & 255;
    int barid = 1 + grp;
    int mi = gw & 1, ni = gw >> 1;
    int g = lane >> 2, tg = lane & 3;

    uint32_t* AH = U + O_A + grp * 8704;
    uint32_t* AL = AH + 4352;
    float* sEA  = F + O_EA + grp * 1024;
    float* GEO  = F + O_GEO + grp * 512;
    int*   sRow = (int*)GEO;
    int*   sCol = (int*)(GEO + 64);
    float* sD2v = GEO + 128;
    float* sDist= GEO + 192;
    float* sPart= GEO + 256;
    float* sDiff= GEO + 320;

    uint32_t uAH = smem_u32(AH), uAL = smem_u32(AL);
    uint32_t uW2H = smem_u32(sW2H), uW2L = smem_u32(sW2L);
    uint32_t uC1H = smem_u32(sC1H), uC1L = smem_u32(sC1L);
    int l15 = lane & 15;
    uint32_t aoff0 = (uint32_t)(((mi * 32 + l15) * 68 + (lane >> 4) * 4) * 4);
    uint32_t aoff1 = aoff0 + 16 * 68 * 4;
    int bj = (lane >> 4) & 1, bg = (lane >> 3) & 1, b8 = lane & 7;
    uint32_t boff0 = (uint32_t)(((ni * 32 + bj * 8 + b8) * 68 + bg * 4) * 4);
    uint32_t boff1 = boff0 + 16 * 68 * 4;

    // =================== PQ pre-phase: P = hf@W1a, Q = hf@W1b ===============
    // stage W1a into sW2 buffers, W1b into sC1 buffers (split bf16, n-major)
    for (int idx = tid; idx < 64 * 128; idx += EDGE_THREADS) {
        int kp = idx >> 7, n = idx & 127;
        uint32_t hi, lo;
        split2(W1[(2 * kp) * Hh + n], W1[(2 * kp + 1) * Hh + n], hi, lo);
        sW2H[n * 68 + kp] = hi;
        sW2L[n * 68 + kp] = lo;
        split2(W1[(128 + 2 * kp) * Hh + n], W1[(128 + 2 * kp + 1) * Hh + n], hi, lo);
        sC1H[n * 68 + kp] = hi;
        sC1L[n * 68 + kp] = lo;
    }
    __syncthreads();

    {
        int tt = blockIdx.x * 2 + grp;
        if (tt < NPQT) {
            int n0 = tt * 64;
            // stage A = hf rows (split bf16)
            {
                int jc = lane;
                #pragma unroll
                for (int r = 0; r < 8; r++) {
                    int row = gw * 8 + r;
                    int node = n0 + row;
                    float4 hv = (node < Nn) ? ((const float4*)(hf + (size_t)node * Hh))[jc]
                                            : make_float4(0.f, 0.f, 0.f, 0.f);
                    uint32_t h0, l0, h1p, l1;
                    split2(hv.x, hv.y, h0, l0);
                    split2(hv.z, hv.w, h1p, l1);
                    *(uint2*)(AH + row * 68 + 2 * jc) = make_uint2(h0, h1p);
                    *(uint2*)(AL + row * 68 + 2 * jc) = make_uint2(l0, l1);
                }
            }
            bar_sync(barid, 256);

            float d[2][4][4];
            #pragma unroll
            for (int pass = 0; pass < 2; pass++) {
                uint32_t uBH = pass ? uC1H : uW2H;
                uint32_t uBL = pass ? uC1L : uW2L;
                float* dstG = pass ? g_Q : g_P;
                #pragma unroll
                for (int mt = 0; mt < 2; mt++)
                    #pragma unroll
                    for (int j = 0; j < 4; j++)
                        d[mt][j][0] = d[mt][j][1] = d[mt][j][2] = d[mt][j][3] = 0.f;
                #pragma unroll
                for (int ks = 0; ks < 8; ks++) {
                    uint32_t koff = (uint32_t)(ks * 32);
                    uint32_t ah0[4], ah1[4], al0[4], al1[4], bh[8], bl[8];
                    ldm4(ah0, uAH + aoff0 + koff);
                    ldm4(ah1, uAH + aoff1 + koff);
                    ldm4(al0, uAL + aoff0 + koff);
                    ldm4(al1, uAL + aoff1 + koff);
                    ldm4(bh,     uBH + boff0 + koff);
                    ldm4(bh + 4, uBH + boff1 + koff);
                    ldm4(bl,     uBL + boff0 + koff);
                    ldm4(bl + 4, uBL + boff1 + koff);
                    #pragma unroll
                    for (int j = 0; j < 4; j++) {
                        uint32_t b0h = bh[j*2], b1h = bh[j*2+1];
                        uint32_t b0l = bl[j*2], b1l = bl[j*2+1];
                        mma16(d[0][j], ah0, b0h, b1h);
                        mma16(d[1][j], ah1, b0h, b1h);
                        mma16(d[0][j], ah0, b0l, b1l);
                        mma16(d[1][j], ah1, b0l, b1l);
                        mma16(d[0][j], al0, b0h, b1h);
                        mma16(d[1][j], al1, b0h, b1h);
                    }
                }
                #pragma unroll
                for (int mt = 0; mt < 2; mt++) {
                    int row0 = mi * 32 + mt * 16 + g;
                    int row1 = row0 + 8;
                    int nd0 = n0 + row0, nd1 = n0 + row1;
                    #pragma unroll
                    for (int j = 0; j < 4; j++) {
                        int c = ni * 32 + j * 8 + 2 * tg;
                        if (nd0 < Nn)
                            *(float2*)(dstG + (size_t)nd0 * Hh + c) = make_float2(d[mt][j][0], d[mt][j][1]);
                        if (nd1 < Nn)
                            *(float2*)(dstG + (size_t)nd1 * Hh + c) = make_float2(d[mt][j][2], d[mt][j][3]);
                    }
                }
            }
        }
    }

    global_bar();   // P/Q visible to all CTAs

    // =================== stage real edge weights ============================
    for (int idx = tid; idx < 64 * 128; idx += EDGE_THREADS) {
        int kp = idx >> 7, n = idx & 127;
        uint32_t hi, lo;
        split2(W2g[(2 * kp) * 128 + n], W2g[(2 * kp + 1) * 128 + n], hi, lo);
        sW2H[n * 68 + kp] = hi;
        sW2L[n * 68 + kp] = lo;
        split2(C1g[(2 * kp) * 128 + n], C1g[(2 * kp + 1) * 128 + n], hi, lo);
        sC1H[n * 68 + kp] = hi;
        sC1L[n * 68 + kp] = lo;
    }
    {
        const float* CWl = g_CW + l * 16 * Hh;
        for (int idx = tid; idx < 16 * Hh; idx += EDGE_THREADS) sCW[idx] = CWl[idx];
    }
    if (tid < Hh) {
        sWd[tid] = W1[256 * Hh + tid];
        sB1[tid] = g_b1eff[l * Hh + tid];
        sB2[tid] = B2[tid];
        sCB[tid] = CB[tid];
        sC2[tid] = C2[tid];
    }
    __syncthreads();

    int stride = gridDim.x * 2;
    int tile0 = blockIdx.x * 2 + grp;

    int pf_r = 0, pf_c = 0;
    float4 pf_ea = make_float4(0.f, 0.f, 0.f, 0.f);
    if (tile0 < NT64) {
        int e0 = tile0 * 64;
        if (gtid < 64) { pf_r = rowi[e0 + gtid]; pf_c = coli[e0 + gtid]; }
        pf_ea = ((const float4*)(ea + (size_t)(e0 + (gtid >> 2)) * 16))[gtid & 3];
    }

    for (int tile = tile0; tile < NT64; tile += stride) {
        if (gtid < 64) {
            int r = pf_r, c = pf_c;
            sRow[gtid] = r; sCol[gtid] = c;
            float dx = xc[r*3+0] - xc[c*3+0];
            float dy = xc[r*3+1] - xc[c*3+1];
            float dz = xc[r*3+2] - xc[c*3+2];
            float d2 = dx*dx + dy*dy + dz*dz;
            sDiff[gtid*3+0] = dx; sDiff[gtid*3+1] = dy; sDiff[gtid*3+2] = dz;
            sD2v[gtid] = d2;
            sDist[gtid] = sqrtf(d2 + EPSf);
            sPart[gtid] = 0.f;
        }
        {
            int e = gtid >> 2, q = gtid & 3;
            float* dst = sEA + e * 16 + q * 4;
            dst[0] = pf_ea.x; dst[1] = pf_ea.y; dst[2] = pf_ea.z; dst[3] = pf_ea.w;
        }
        bar_sync(barid, 256);

        {
            int tn = tile + stride;
            if (tn < NT64) {
                int e0n = tn * 64;
                if (gtid < 64) { pf_r = rowi[e0n + gtid]; pf_c = coli[e0n + gtid]; }
                pf_ea = ((const float4*)(ea + (size_t)(e0n + (gtid >> 2)) * 16))[gtid & 3];
            }
        }

        {
            int jc = lane;
            float acc[8][4];
            float4 wd = ((const float4*)sWd)[jc];
            float4 b1 = ((const float4*)sB1)[jc];
            #pragma unroll
            for (int r = 0; r < 8; r++) {
                int e = gw * 8 + r;
                int rw = sRow[e], cl = sCol[e];
                float d2 = sD2v[e];
                float4 pp = ((const float4*)(g_P + (size_t)rw * Hh))[jc];
                float4 qq = ((const float4*)(g_Q + (size_t)cl * Hh))[jc];
                acc[r][0] = pp.x + qq.x + fmaf(d2, wd.x, b1.x);
                acc[r][1] = pp.y + qq.y + fmaf(d2, wd.y, b1.y);
                acc[r][2] = pp.z + qq.z + fmaf(d2, wd.z, b1.z);
                acc[r][3] = pp.w + qq.w + fmaf(d2, wd.w, b1.w);
            }
            const float4* CW4 = (const float4*)sCW;
            #pragma unroll
            for (int k = 0; k < 16; k++) {
                float4 cw = CW4[k * 32 + jc];
                #pragma unroll
                for (int r = 0; r < 8; r++) {
                    float a = sEA[(gw * 8 + r) * 16 + k];
                    acc[r][0] = fmaf(a, cw.x, acc[r][0]);
                    acc[r][1] = fmaf(a, cw.y, acc[r][1]);
                    acc[r][2] = fmaf(a, cw.z, acc[r][2]);
                    acc[r][3] = fmaf(a, cw.w, acc[r][3]);
                }
            }
            #pragma unroll
            for (int r = 0; r < 8; r++) {
                int e = gw * 8 + r;
                float s0 = siluf(acc[r][0]), s1 = siluf(acc[r][1]);
                float s2 = siluf(acc[r][2]), s3 = siluf(acc[r][3]);
                uint32_t h0, l0, h1p, l1;
                split2(s0, s1, h0, l0);
                split2(s2, s3, h1p, l1);
                *(uint2*)(AH + e * 68 + 2 * jc) = make_uint2(h0, h1p);
                *(uint2*)(AL + e * 68 + 2 * jc) = make_uint2(l0, l1);
            }
        }
        bar_sync(barid, 256);

        float d[2][4][4];

        #pragma unroll
        for (int mt = 0; mt < 2; mt++)
            #pragma unroll
            for (int j = 0; j < 4; j++)
                d[mt][j][0] = d[mt][j][1] = d[mt][j][2] = d[mt][j][3] = 0.f;
        #pragma unroll
        for (int ks = 0; ks < 8; ks++) {
            uint32_t koff = (uint32_t)(ks * 32);
            uint32_t ah0[4], ah1[4], al0[4], al1[4], bh[8], bl[8];
            ldm4(ah0, uAH + aoff0 + koff);
            ldm4(ah1, uAH + aoff1 + koff);
            ldm4(al0, uAL + aoff0 + koff);
            ldm4(al1, uAL + aoff1 + koff);
            ldm4(bh,     uW2H + boff0 + koff);
            ldm4(bh + 4, uW2H + boff1 + koff);
            ldm4(bl,     uW2L + boff0 + koff);
            ldm4(bl + 4, uW2L + boff1 + koff);
            #pragma unroll
            for (int j = 0; j < 4; j++) {
                uint32_t b0h = bh[j*2], b1h = bh[j*2+1];
                uint32_t b0l = bl[j*2], b1l = bl[j*2+1];
                mma16(d[0][j], ah0, b0h, b1h);
                mma16(d[1][j], ah1, b0h, b1h);
                mma16(d[0][j], ah0, b0l, b1l);
                mma16(d[1][j], ah1, b0l, b1l);
                mma16(d[0][j], al0, b0h, b1h);
                mma16(d[1][j], al1, b0h, b1h);
            }
        }
        bar_sync(barid, 256);

        #pragma unroll
        for (int mt = 0; mt < 2; mt++) {
            int er0 = mi * 32 + mt * 16 + g;
            int er1 = er0 + 8;
            int rw0 = sRow[er0], rw1 = sRow[er1];
            #pragma unroll
            for (int j = 0; j < 4; j++) {
                int c = ni * 32 + j * 8 + 2 * tg;
                float m00 = siluf(d[mt][j][0] + sB2[c]);
                float m01 = siluf(d[mt][j][1] + sB2[c + 1]);
                float m10 = siluf(d[mt][j][2] + sB2[c]);
                float m11 = siluf(d[mt][j][3] + sB2[c + 1]);
                asm volatile("red.global.add.v2.f32 [%0], {%1,%2};"
                             :: "l"(g_aggmsg + (size_t)rw0 * Hh + c), "f"(m00), "f"(m01) : "memory");
                asm volatile("red.global.add.v2.f32 [%0], {%1,%2};"
                             :: "l"(g_aggmsg + (size_t)rw1 * Hh + c), "f"(m10), "f"(m11) : "memory");
                uint32_t hi, lo;
                split2(m00, m01, hi, lo);
                AH[er0 * 68 + (c >> 1)] = hi;
                AL[er0 * 68 + (c >> 1)] = lo;
                split2(m10, m11, hi, lo);
                AH[er1 * 68 + (c >> 1)] = hi;
                AL[er1 * 68 + (c >> 1)] = lo;
            }
        }
        bar_sync(barid, 256);

        #pragma unroll
        for (int mt = 0; mt < 2; mt++)
            #pragma unroll
            for (int j = 0; j < 4; j++)
                d[mt][j][0] = d[mt][j][1] = d[mt][j][2] = d[mt][j][3] = 0.f;
        #pragma unroll
        for (int ks = 0; ks < 8; ks++) {
            uint32_t koff = (uint32_t)(ks * 32);
            uint32_t ah0[4], ah1[4], al0[4], al1[4], bh[8], bl[8];
            ldm4(ah0, uAH + aoff0 + koff);
            ldm4(ah1, uAH + aoff1 + koff);
            ldm4(al0, uAL + aoff0 + koff);
            ldm4(al1, uAL + aoff1 + koff);
            ldm4(bh,     uC1H + boff0 + koff);
            ldm4(bh + 4, uC1H + boff1 + koff);
            ldm4(bl,     uC1L + boff0 + koff);
            ldm4(bl + 4, uC1L + boff1 + koff);
            #pragma unroll
            for (int j = 0; j < 4; j++) {
                uint32_t b0h = bh[j*2], b1h = bh[j*2+1];
                uint32_t b0l = bl[j*2], b1l = bl[j*2+1];
                mma16(d[0][j], ah0, b0h, b1h);
                mma16(d[1][j], ah1, b0h, b1h);
                mma16(d[0][j], ah0, b0l, b1l);
                mma16(d[1][j], ah1, b0l, b1l);
                mma16(d[0][j], al0, b0h, b1h);
                mma16(d[1][j], al1, b0h, b1h);
            }
        }

        {
            float prt[2][2];
            prt[0][0] = prt[0][1] = prt[1][0] = prt[1][1] = 0.f;
            #pragma unroll
            for (int mt = 0; mt < 2; mt++) {
                #pragma unroll
                for (int j = 0; j < 4; j++) {
                    int c = ni * 32 + j * 8 + 2 * tg;
                    float c2a = sC2[c], c2b = sC2[c + 1];
                    float u00 = siluf(d[mt][j][0] + sCB[c]);
                    float u01 = siluf(d[mt][j][1] + sCB[c + 1]);
                    float u10 = siluf(d[mt][j][2] + sCB[c]);
                    float u11 = siluf(d[mt][j][3] + sCB[c + 1]);
                    prt[mt][0] += u00 * c2a + u01 * c2b;
                    prt[mt][1] += u10 * c2a + u11 * c2b;
                }
            }
            #pragma unroll
            for (int mt = 0; mt < 2; mt++) {
                #pragma unroll
                for (int rh = 0; rh < 2; rh++) {
                    float pv = prt[mt][rh];
                    pv += __shfl_xor_sync(0xffffffffu, pv, 1);
                    pv += __shfl_xor_sync(0xffffffffu, pv, 2);
                    if (tg == 0)
                        atomicAdd(&sPart[mi * 32 + mt * 16 + rh * 8 + g], pv);
                }
            }
        }
        bar_sync(barid, 256);

        if (gtid < 64) {
            float wsc = tanhf(sPart[gtid]);
            float s = wsc / (sDist[gtid] + EPSf);
            int rw = sRow[gtid];
            atomicAdd(&g_aggtrans[rw * 3 + 0], sDiff[gtid * 3 + 0] * s);
            atomicAdd(&g_aggtrans[rw * 3 + 1], sDiff[gtid * 3 + 1] * s);
            atomicAdd(&g_aggtrans[rw * 3 + 2], sDiff[gtid * 3 + 2] * s);
        }
        bar_sync(barid, 256);
    }
}

// ---------------- node update kernel (also zeroes agg after reading) ---------
__global__ void __launch_bounds__(256, 1) node_kernel(
    const float* __restrict__ mask,
    const float* __restrict__ N1w, const float* __restrict__ NB1,
    const float* __restrict__ N2w, const float* __restrict__ NB2,
    int selr, int selw) {
    extern __shared__ float sm[];
    float* sIn = sm;
    float* sH  = sIn + 64 * 256;
    const float* hc = g_hfeat[selr];
    float* hn = g_hfeat[selw];
    int tid = threadIdx.x;
    int n0 = blockIdx.x * 64;

    for (int idx = tid; idx < 64 * Hh; idx += 256) {
        int i = idx >> 7, k = idx & 127;
        int node = n0 + i;
        float hv = 0.f, av = 0.f;
        if (node < Nn) {
            hv = hc[node * Hh + k];
            av = g_aggmsg[node * Hh + k];
            g_aggmsg[node * Hh + k] = 0.f;
        }
        sIn[i * 256 + k] = hv;
        sIn[i * 256 + 128 + k] = av;
    }
    __syncthreads();

    int jc = tid & 31, wp = tid >> 5;
    {
        float acc[8][4];
        #pragma unroll
        for (int r = 0; r < 8; r++) { acc[r][0]=acc[r][1]=acc[r][2]=acc[r][3]=0.f; }
        const float4* Wv = (const float4*)N1w;
        for (int k = 0; k < 256; k++) {
            float4 w = Wv[k * 32 + jc];
            #pragma unroll
            for (int r = 0; r < 8; r++) {
                float a = sIn[(wp * 8 + r) * 256 + k];
                acc[r][0]=fmaf(a,w.x,acc[r][0]); acc[r][1]=fmaf(a,w.y,acc[r][1]);
                acc[r][2]=fmaf(a,w.z,acc[r][2]); acc[r][3]=fmaf(a,w.w,acc[r][3]);
            }
        }
        float4 bv = ((const float4*)NB1)[jc];
        #pragma unroll
        for (int r = 0; r < 8; r++) {
            float4 o;
            o.x = siluf(acc[r][0]+bv.x); o.y = siluf(acc[r][1]+bv.y);
            o.z = siluf(acc[r][2]+bv.z); o.w = siluf(acc[r][3]+bv.w);
            ((float4*)sH)[(wp * 8 + r) * 32 + jc] = o;
        }
    }
    __syncthreads();
    {
        float acc[8][4];
        #pragma unroll
        for (int r = 0; r < 8; r++) { acc[r][0]=acc[r][1]=acc[r][2]=acc[r][3]=0.f; }
        const float4* Wv = (const float4*)N2w;
        for (int k = 0; k < Hh; k++) {
            float4 w = Wv[k * 32 + jc];
            #pragma unroll
            for (int r = 0; r < 8; r++) {
                float a = sH[(wp * 8 + r) * Hh + k];
                acc[r][0]=fmaf(a,w.x,acc[r][0]); acc[r][1]=fmaf(a,w.y,acc[r][1]);
                acc[r][2]=fmaf(a,w.z,acc[r][2]); acc[r][3]=fmaf(a,w.w,acc[r][3]);
            }
        }
        float4 bv = ((const float4*)NB2)[jc];
        #pragma unroll
        for (int r = 0; r < 8; r++) {
            int node = n0 + wp * 8 + r;
            if (node < Nn) {
                float4 hv = ((const float4*)(hc + node * Hh))[jc];
                float4 o;
                o.x = hv.x + acc[r][0] + bv.x; o.y = hv.y + acc[r][1] + bv.y;
                o.z = hv.z + acc[r][2] + bv.z; o.w = hv.w + acc[r][3] + bv.w;
                ((float4*)(hn + node * Hh))[jc] = o;
            }
        }
    }
    if (tid < 64) {
        int node = n0 + tid;
        if (node < Nn) {
            float mk = mask[node];
            const float* xr = g_x[selr];
            float* xw = g_x[selw];
            float ax = g_aggtrans[node*3+0];
            float ay = g_aggtrans[node*3+1];
            float az = g_aggtrans[node*3+2];
            xw[node*3+0] = xr[node*3+0] + ax * mk;
            xw[node*3+1] = xr[node*3+1] + ay * mk;
            xw[node*3+2] = xr[node*3+2] + az * mk;
            g_aggtrans[node*3+0] = 0.f;
            g_aggtrans[node*3+1] = 0.f;
            g_aggtrans[node*3+2] = 0.f;
        }
    }
}

// ---------------- final ------------------------------------------------------
__global__ void final_kernel(const float* __restrict__ x_in,
                             const float* __restrict__ mask,
                             float* __restrict__ out) {
    int i = blockIdx.x * 256 + threadIdx.x;
    if (i < Nn) {
        float mk = mask[i];
        out[i*3+0] = (g_x[0][i*3+0] - x_in[i*3+0]) * mk;
        out[i*3+1] = (g_x[0][i*3+1] - x_in[i*3+1]) * mk;
        out[i*3+2] = (g_x[0][i*3+2] - x_in[i*3+2]) * mk;
    }
}

// ---------------- launcher ----------------------------------------------------
extern "C" void kernel_launch(void* const* d_in, const int* in_sizes, int n_in,
                              void* d_out, int out_size) {
    const float* h          = (const float*)d_in[0];
    const float* x          = (const float*)d_in[1];
    const int*   edge_index = (const int*)  d_in[2];
    const float* edge_attr  = (const float*)d_in[3];
    const float* t          = (const float*)d_in[4];
    const float* mask       = (const float*)d_in[5];
    const float* time_w1    = (const float*)d_in[6];
    const float* time_b1    = (const float*)d_in[7];
    const float* time_w2    = (const float*)d_in[8];
    const float* time_b2    = (const float*)d_in[9];
    const float* node_emb_w = (const float*)d_in[10];
    const float* node_emb_b = (const float*)d_in[11];
    const float* edge_emb_w = (const float*)d_in[12];
    const float* edge_emb_b = (const float*)d_in[13];
    const float* ew1 = (const float*)d_in[14];
    const float* eb1 = (const float*)d_in[15];
    const float* ew2 = (const float*)d_in[16];
    const float* eb2 = (const float*)d_in[17];
    const float* cw1 = (const float*)d_in[18];
    const float* cb1 = (const float*)d_in[19];
    const float* cw2 = (const float*)d_in[20];
    const float* nw1 = (const float*)d_in[21];
    const float* nb1 = (const float*)d_in[22];
    const float* nw2 = (const float*)d_in[23];
    const float* nb2 = (const float*)d_in[24];
    float* out = (float*)d_out;

    const int* rowi = edge_index;
    const int* coli = edge_index + Ee;

    const int SMEM_EDGE = SMEM_EDGE_WORDS * 4;
    const int SMEM_NODE = (64 * 256 + 64 * Hh) * 4;
    const int SMEM_HF   = 64 * 64 * 4;

    cudaFuncSetAttribute(edge_mma_kernel, cudaFuncAttributeMaxDynamicSharedMemorySize, SMEM_EDGE);
    cudaFuncSetAttribute(node_kernel, cudaFuncAttributeMaxDynamicSharedMemorySize, SMEM_NODE);

    // init: temb | zero agg | setup x4 layers
    init_kernel<<<1 + NB_AGG + 4, 256>>>(t, time_w1, time_b1, time_w2, time_b2,
                                         edge_emb_w, edge_emb_b, ew1, eb1);
    // emb: hfeat | copyx
    emb_kernel<<<NB_HF + NB_CX, 256, SMEM_HF>>>(h, node_emb_w, node_emb_b, x);

    for (int l = 0; l < 4; l++) {
        int sr = l & 1;
        int sw = 1 - sr;
        edge_mma_kernel<<<EDGE_GRID, EDGE_THREADS, SMEM_EDGE>>>(
            rowi, coli, edge_attr, ew1 + (size_t)l * 385 * Hh,
            ew2 + (size_t)l * Hh * Hh, eb2 + l * Hh,
            cw1 + (size_t)l * Hh * Hh, cb1 + l * Hh,
            cw2 + (size_t)l * Hh,
            l);
        node_kernel<<<157, 256, SMEM_NODE>>>(
            mask,
            nw1 + (size_t)l * 256 * Hh, nb1 + l * Hh,
            nw2 + (size_t)l * Hh * Hh,  nb2 + l * Hh,
            sr, sw);
    }

    final_kernel<<<(Nn + 255) / 256, 256>>>(x, mask, out);
}

// round 15
// speedup vs baseline: 1.1069x; 1.0917x over previous
#include <cuda_runtime.h>
#include <cuda_bf16.h>
#include <math.h>
#include <stdint.h>

#define Nn 10000
#define Ee 320000
#define Hh 128
#define EPSf 1e-8f
#define NT64 5000
#define EDGE_GRID 148
#define EDGE_THREADS 512
#define NPQT 157           // 64-node tiles

// ---------------- scratch ----------------------------------------------------
__device__ float g_temb[Hh];
__device__ float g_hfeat[2][Nn * Hh];
__device__ float g_x[2][Nn * 3];
__device__ float g_P[Nn * Hh];
__device__ float g_Q[Nn * Hh];
__device__ float g_CW[4 * 16 * Hh];
__device__ float g_b1eff[4 * Hh];
__device__ float g_aggmsg[Nn * Hh];
__device__ float g_aggtrans[Nn * 3];
__device__ uint32_t g_TH[(size_t)Nn * 64];   // t (silu node hidden) bf16-hi pairs
__device__ uint32_t g_TL[(size_t)Nn * 64];   // t bf16-lo pairs
__device__ int g_bar_cnt = 0;
__device__ volatile int g_bar_epoch = 0;

__device__ __forceinline__ float siluf(float x) { return x / (1.0f + __expf(-x)); }

__device__ __forceinline__ void mma16(float* d, const uint32_t* a, uint32_t b0, uint32_t b1) {
    asm volatile("mma.sync.aligned.m16n8k16.row.col.f32.bf16.bf16.f32 "
        "{%0,%1,%2,%3}, {%4,%5,%6,%7}, {%8,%9}, {%0,%1,%2,%3};"
        : "+f"(d[0]), "+f"(d[1]), "+f"(d[2]), "+f"(d[3])
        : "r"(a[0]), "r"(a[1]), "r"(a[2]), "r"(a[3]), "r"(b0), "r"(b1));
}

__device__ __forceinline__ void ldm4(uint32_t* r, uint32_t addr) {
    asm volatile("ldmatrix.sync.aligned.m8n8.x4.shared.b16 {%0,%1,%2,%3}, [%4];"
        : "=r"(r[0]), "=r"(r[1]), "=r"(r[2]), "=r"(r[3]) : "r"(addr));
}

__device__ __forceinline__ uint32_t smem_u32(const void* p) {
    uint32_t a;
    asm("{ .reg .u64 t; cvta.to.shared.u64 t, %1; cvt.u32.u64 %0, t; }" : "=r"(a) : "l"(p));
    return a;
}

__device__ __forceinline__ void split2(float x0, float x1, uint32_t& hi, uint32_t& lo) {
    __nv_bfloat162 h = __floats2bfloat162_rn(x0, x1);
    float h0 = __bfloat162float(__low2bfloat16(h));
    float h1 = __bfloat162float(__high2bfloat16(h));
    __nv_bfloat162 l = __floats2bfloat162_rn(x0 - h0, x1 - h1);
    hi = *(uint32_t*)&h;
    lo = *(uint32_t*)&l;
}

__device__ __forceinline__ void bar_sync(int id, int cnt) {
    asm volatile("bar.sync %0, %1;" :: "r"(id), "r"(cnt) : "memory");
}

// epoch-based device-wide barrier (all CTAs resident)
__device__ __forceinline__ void global_bar() {
    __syncthreads();
    if (threadIdx.x == 0) {
        int e = g_bar_epoch;
        __threadfence();
        int v = atomicAdd(&g_bar_cnt, 1);
        if (v == (int)gridDim.x - 1) {
            g_bar_cnt = 0;
            __threadfence();
            g_bar_epoch = e + 1;
        } else {
            while (g_bar_epoch == e) __nanosleep(64);
        }
    }
    __syncthreads();
    __threadfence();
}

// ================= init = temb | zero agg | setup x4 =========================
#define NB_AGG 5118
__global__ void __launch_bounds__(256, 1) init_kernel(
    const float* __restrict__ t,
    const float* __restrict__ w1, const float* __restrict__ b1,
    const float* __restrict__ w2, const float* __restrict__ b2,
    const float* __restrict__ eew, const float* __restrict__ eeb,
    const float* __restrict__ ew1, const float* __restrict__ eb1) {
    int b = blockIdx.x, tid = threadIdx.x;
    if (b == 0) {
        __shared__ float sh[Hh];
        float tv = t[0];
        if (tid < Hh) sh[tid] = siluf(tv * w1[tid] + b1[tid]);
        __syncthreads();
        if (tid < Hh) {
            float acc = b2[tid];
            #pragma unroll 4
            for (int k = 0; k < Hh; k++) acc = fmaf(sh[k], w2[k * Hh + tid], acc);
            g_temb[tid] = acc;
        }
    } else if (b <= NB_AGG) {
        int i = (b - 1) * 256 + tid;
        if (i < Nn * Hh) g_aggmsg[i] = 0.f;
        else if (i < Nn * Hh + Nn * 3) g_aggtrans[i - Nn * Hh] = 0.f;
    } else {
        int L = b - NB_AGG - 1;
        const float* W1 = ew1 + (size_t)L * 385 * Hh;
        const float* B1 = eb1 + L * Hh;
        float* CW = g_CW + L * 16 * Hh;
        float* be = g_b1eff + L * Hh;
        for (int o = tid; o < 16 * Hh; o += 256) {
            int i = o >> 7, j = o & 127;
            float acc = 0.f;
            #pragma unroll 4
            for (int k = 0; k < Hh; k++)
                acc = fmaf(eew[i * Hh + k], W1[(257 + k) * Hh + j], acc);
            CW[o] = acc;
        }
        if (tid < Hh) {
            float acc = B1[tid];
            #pragma unroll 4
            for (int k = 0; k < Hh; k++)
                acc = fmaf(eeb[k], W1[(257 + k) * Hh + tid], acc);
            be[tid] = acc;
        }
    }
}

// ====== emb: hfeat(h@W+b+temb) | copyx =======================================
#define NB_HF 157
#define NB_CX 118
__global__ void __launch_bounds__(256, 1) emb_kernel(
    const float* __restrict__ h, const float* __restrict__ W, const float* __restrict__ B,
    const float* __restrict__ x) {
    int b = blockIdx.x, tid = threadIdx.x;
    if (b < NB_HF) {
        extern __shared__ float sIn[];
        int n0 = b * 64;
        for (int idx = tid; idx < 64 * 64; idx += 256) {
            int i = idx >> 6, k = idx & 63;
            int node = n0 + i;
            sIn[idx] = (node < Nn) ? h[node * 64 + k] : 0.f;
        }
        __syncthreads();
        int jc = tid & 31, wp = tid >> 5;
        float acc[8][4];
        #pragma unroll
        for (int r = 0; r < 8; r++) { acc[r][0]=acc[r][1]=acc[r][2]=acc[r][3]=0.f; }
        const float4* Wv = (const float4*)W;
        for (int k = 0; k < 64; k++) {
            float4 w = Wv[k * 32 + jc];
            #pragma unroll
            for (int r = 0; r < 8; r++) {
                float a = sIn[(wp * 8 + r) * 64 + k];
                acc[r][0]=fmaf(a,w.x,acc[r][0]); acc[r][1]=fmaf(a,w.y,acc[r][1]);
                acc[r][2]=fmaf(a,w.z,acc[r][2]); acc[r][3]=fmaf(a,w.w,acc[r][3]);
            }
        }
        float4 bv = ((const float4*)B)[jc];
        float4 tv = ((const float4*)g_temb)[jc];
        #pragma unroll
        for (int r = 0; r < 8; r++) {
            int node = n0 + wp * 8 + r;
            if (node < Nn) {
                float4 o;
                o.x = acc[r][0]+bv.x+tv.x; o.y = acc[r][1]+bv.y+tv.y;
                o.z = acc[r][2]+bv.z+tv.z; o.w = acc[r][3]+bv.w+tv.w;
                ((float4*)(g_hfeat[0] + node * Hh))[jc] = o;
            }
        }
    } else {
        int i = (b - NB_HF) * 256 + tid;
        if (i < Nn * 3) g_x[0][i] = x[i];
    }
}

// ============ edge kernel: PQ mma pre-phase + dual-pipeline edge tiles =======
#define O_W2H  0
#define O_W2L  8704
#define O_C1H  17408
#define O_C1L  26112
#define O_A    34816
#define O_EA   52224
#define O_CW   54272
#define O_WD   56320
#define O_B1   56448
#define O_B2   56576
#define O_CB   56704
#define O_C2   56832
#define O_GEO  56960
#define SMEM_EDGE_WORDS 57984

__global__ void __launch_bounds__(EDGE_THREADS, 1) edge_mma_kernel(
    const int* __restrict__ rowi, const int* __restrict__ coli,
    const float* __restrict__ ea,
    const float* __restrict__ W1,
    const float* __restrict__ W2g, const float* __restrict__ B2,
    const float* __restrict__ C1g, const float* __restrict__ CB,
    const float* __restrict__ C2, int l) {
    extern __shared__ float F[];
    uint32_t* U = (uint32_t*)F;
    uint32_t* sW2H = U + O_W2H;
    uint32_t* sW2L = U + O_W2L;
    uint32_t* sC1H = U + O_C1H;
    uint32_t* sC1L = U + O_C1L;
    float* sCW = F + O_CW;
    float* sWd = F + O_WD;
    float* sB1 = F + O_B1;
    float* sB2 = F + O_B2;
    float* sCB = F + O_CB;
    float* sC2 = F + O_C2;

    int tid = threadIdx.x;
    int lane = tid & 31, w = tid >> 5;
    int sel = l & 1;

    const float* xc = g_x[sel];
    const float* hf = g_hfeat[sel];

    int grp = w >> 3;
    int gw = w & 7;
    int gtid = tid & 255;
    int barid = 1 + grp;
    int mi = gw & 1, ni = gw >> 1;
    int g = lane >> 2, tg = lane & 3;

    uint32_t* AH = U + O_A + grp * 8704;
    uint32_t* AL = AH + 4352;
    float* sEA  = F + O_EA + grp * 1024;
    float* GEO  = F + O_GEO + grp * 512;
    int*   sRow = (int*)GEO;
    int*   sCol = (int*)(GEO + 64);
    float* sD2v = GEO + 128;
    float* sDist= GEO + 192;
    float* sPart= GEO + 256;
    float* sDiff= GEO + 320;

    uint32_t uAH = smem_u32(AH), uAL = smem_u32(AL);
    uint32_t uW2H = smem_u32(sW2H), uW2L = smem_u32(sW2L);
    uint32_t uC1H = smem_u32(sC1H), uC1L = smem_u32(sC1L);
    int l15 = lane & 15;
    uint32_t aoff0 = (uint32_t)(((mi * 32 + l15) * 68 + (lane >> 4) * 4) * 4);
    uint32_t aoff1 = aoff0 + 16 * 68 * 4;
    int bj = (lane >> 4) & 1, bg = (lane >> 3) & 1, b8 = lane & 7;
    uint32_t boff0 = (uint32_t)(((ni * 32 + bj * 8 + b8) * 68 + bg * 4) * 4);
    uint32_t boff1 = boff0 + 16 * 68 * 4;

    // ---- PQ pre-phase: P = hf@W1a, Q = hf@W1b ----
    for (int idx = tid; idx < 64 * 128; idx += EDGE_THREADS) {
        int kp = idx >> 7, n = idx & 127;
        uint32_t hi, lo;
        split2(W1[(2 * kp) * Hh + n], W1[(2 * kp + 1) * Hh + n], hi, lo);
        sW2H[n * 68 + kp] = hi;
        sW2L[n * 68 + kp] = lo;
        split2(W1[(128 + 2 * kp) * Hh + n], W1[(128 + 2 * kp + 1) * Hh + n], hi, lo);
        sC1H[n * 68 + kp] = hi;
        sC1L[n * 68 + kp] = lo;
    }
    __syncthreads();

    {
        int tt = blockIdx.x * 2 + grp;
        if (tt < NPQT) {
            int n0 = tt * 64;
            {
                int jc = lane;
                #pragma unroll
                for (int r = 0; r < 8; r++) {
                    int row = gw * 8 + r;
                    int node = n0 + row;
                    float4 hv = (node < Nn) ? ((const float4*)(hf + (size_t)node * Hh))[jc]
                                            : make_float4(0.f, 0.f, 0.f, 0.f);
                    uint32_t h0, l0, h1p, l1;
                    split2(hv.x, hv.y, h0, l0);
                    split2(hv.z, hv.w, h1p, l1);
                    *(uint2*)(AH + row * 68 + 2 * jc) = make_uint2(h0, h1p);
                    *(uint2*)(AL + row * 68 + 2 * jc) = make_uint2(l0, l1);
                }
            }
            bar_sync(barid, 256);

            float d[2][4][4];
            #pragma unroll
            for (int pass = 0; pass < 2; pass++) {
                uint32_t uBH = pass ? uC1H : uW2H;
                uint32_t uBL = pass ? uC1L : uW2L;
                float* dstG = pass ? g_Q : g_P;
                #pragma unroll
                for (int mt = 0; mt < 2; mt++)
                    #pragma unroll
                    for (int j = 0; j < 4; j++)
                        d[mt][j][0] = d[mt][j][1] = d[mt][j][2] = d[mt][j][3] = 0.f;
                #pragma unroll
                for (int ks = 0; ks < 8; ks++) {
                    uint32_t koff = (uint32_t)(ks * 32);
                    uint32_t ah0[4], ah1[4], al0[4], al1[4], bh[8], bl[8];
                    ldm4(ah0, uAH + aoff0 + koff);
                    ldm4(ah1, uAH + aoff1 + koff);
                    ldm4(al0, uAL + aoff0 + koff);
                    ldm4(al1, uAL + aoff1 + koff);
                    ldm4(bh,     uBH + boff0 + koff);
                    ldm4(bh + 4, uBH + boff1 + koff);
                    ldm4(bl,     uBL + boff0 + koff);
                    ldm4(bl + 4, uBL + boff1 + koff);
                    #pragma unroll
                    for (int j = 0; j < 4; j++) {
                        uint32_t b0h = bh[j*2], b1h = bh[j*2+1];
                        uint32_t b0l = bl[j*2], b1l = bl[j*2+1];
                        mma16(d[0][j], ah0, b0h, b1h);
                        mma16(d[1][j], ah1, b0h, b1h);
                        mma16(d[0][j], ah0, b0l, b1l);
                        mma16(d[1][j], ah1, b0l, b1l);
                        mma16(d[0][j], al0, b0h, b1h);
                        mma16(d[1][j], al1, b0h, b1h);
                    }
                }
                #pragma unroll
                for (int mt = 0; mt < 2; mt++) {
                    int row0 = mi * 32 + mt * 16 + g;
                    int row1 = row0 + 8;
                    int nd0 = n0 + row0, nd1 = n0 + row1;
                    #pragma unroll
                    for (int j = 0; j < 4; j++) {
                        int c = ni * 32 + j * 8 + 2 * tg;
                        if (nd0 < Nn)
                            *(float2*)(dstG + (size_t)nd0 * Hh + c) = make_float2(d[mt][j][0], d[mt][j][1]);
                        if (nd1 < Nn)
                            *(float2*)(dstG + (size_t)nd1 * Hh + c) = make_float2(d[mt][j][2], d[mt][j][3]);
                    }
                }
            }
        }
    }

    global_bar();

    // ---- stage real edge weights ----
    for (int idx = tid; idx < 64 * 128; idx += EDGE_THREADS) {
        int kp = idx >> 7, n = idx & 127;
        uint32_t hi, lo;
        split2(W2g[(2 * kp) * 128 + n], W2g[(2 * kp + 1) * 128 + n], hi, lo);
        sW2H[n * 68 + kp] = hi;
        sW2L[n * 68 + kp] = lo;
        split2(C1g[(2 * kp) * 128 + n], C1g[(2 * kp + 1) * 128 + n], hi, lo);
        sC1H[n * 68 + kp] = hi;
        sC1L[n * 68 + kp] = lo;
    }
    {
        const float* CWl = g_CW + l * 16 * Hh;
        for (int idx = tid; idx < 16 * Hh; idx += EDGE_THREADS) sCW[idx] = CWl[idx];
    }
    if (tid < Hh) {
        sWd[tid] = W1[256 * Hh + tid];
        sB1[tid] = g_b1eff[l * Hh + tid];
        sB2[tid] = B2[tid];
        sCB[tid] = CB[tid];
        sC2[tid] = C2[tid];
    }
    __syncthreads();

    int stride = gridDim.x * 2;
    int tile0 = blockIdx.x * 2 + grp;

    int pf_r = 0, pf_c = 0;
    float4 pf_ea = make_float4(0.f, 0.f, 0.f, 0.f);
    if (tile0 < NT64) {
        int e0 = tile0 * 64;
        if (gtid < 64) { pf_r = rowi[e0 + gtid]; pf_c = coli[e0 + gtid]; }
        pf_ea = ((const float4*)(ea + (size_t)(e0 + (gtid >> 2)) * 16))[gtid & 3];
    }

    for (int tile = tile0; tile < NT64; tile += stride) {
        if (gtid < 64) {
            int r = pf_r, c = pf_c;
            sRow[gtid] = r; sCol[gtid] = c;
            float dx = xc[r*3+0] - xc[c*3+0];
            float dy = xc[r*3+1] - xc[c*3+1];
            float dz = xc[r*3+2] - xc[c*3+2];
            float d2 = dx*dx + dy*dy + dz*dz;
            sDiff[gtid*3+0] = dx; sDiff[gtid*3+1] = dy; sDiff[gtid*3+2] = dz;
            sD2v[gtid] = d2;
            sDist[gtid] = sqrtf(d2 + EPSf);
            sPart[gtid] = 0.f;
        }
        {
            int e = gtid >> 2, q = gtid & 3;
            float* dst = sEA + e * 16 + q * 4;
            dst[0] = pf_ea.x; dst[1] = pf_ea.y; dst[2] = pf_ea.z; dst[3] = pf_ea.w;
        }
        bar_sync(barid, 256);

        {
            int tn = tile + stride;
            if (tn < NT64) {
                int e0n = tn * 64;
                if (gtid < 64) { pf_r = rowi[e0n + gtid]; pf_c = coli[e0n + gtid]; }
                pf_ea = ((const float4*)(ea + (size_t)(e0n + (gtid >> 2)) * 16))[gtid & 3];
            }
        }

        {
            int jc = lane;
            float acc[8][4];
            float4 wd = ((const float4*)sWd)[jc];
            float4 b1 = ((const float4*)sB1)[jc];
            #pragma unroll
            for (int r = 0; r < 8; r++) {
                int e = gw * 8 + r;
                int rw = sRow[e], cl = sCol[e];
                float d2 = sD2v[e];
                float4 pp = ((const float4*)(g_P + (size_t)rw * Hh))[jc];
                float4 qq = ((const float4*)(g_Q + (size_t)cl * Hh))[jc];
                acc[r][0] = pp.x + qq.x + fmaf(d2, wd.x, b1.x);
                acc[r][1] = pp.y + qq.y + fmaf(d2, wd.y, b1.y);
                acc[r][2] = pp.z + qq.z + fmaf(d2, wd.z, b1.z);
                acc[r][3] = pp.w + qq.w + fmaf(d2, wd.w, b1.w);
            }
            const float4* CW4 = (const float4*)sCW;
            #pragma unroll
            for (int k = 0; k < 16; k++) {
                float4 cw = CW4[k * 32 + jc];
                #pragma unroll
                for (int r = 0; r < 8; r++) {
                    float a = sEA[(gw * 8 + r) * 16 + k];
                    acc[r][0] = fmaf(a, cw.x, acc[r][0]);
                    acc[r][1] = fmaf(a, cw.y, acc[r][1]);
                    acc[r][2] = fmaf(a, cw.z, acc[r][2]);
                    acc[r][3] = fmaf(a, cw.w, acc[r][3]);
                }
            }
            #pragma unroll
            for (int r = 0; r < 8; r++) {
                int e = gw * 8 + r;
                float s0 = siluf(acc[r][0]), s1 = siluf(acc[r][1]);
                float s2 = siluf(acc[r][2]), s3 = siluf(acc[r][3]);
                uint32_t h0, l0, h1p, l1;
                split2(s0, s1, h0, l0);
                split2(s2, s3, h1p, l1);
                *(uint2*)(AH + e * 68 + 2 * jc) = make_uint2(h0, h1p);
                *(uint2*)(AL + e * 68 + 2 * jc) = make_uint2(l0, l1);
            }
        }
        bar_sync(barid, 256);

        float d[2][4][4];

        #pragma unroll
        for (int mt = 0; mt < 2; mt++)
            #pragma unroll
            for (int j = 0; j < 4; j++)
                d[mt][j][0] = d[mt][j][1] = d[mt][j][2] = d[mt][j][3] = 0.f;
        #pragma unroll
        for (int ks = 0; ks < 8; ks++) {
            uint32_t koff = (uint32_t)(ks * 32);
            uint32_t ah0[4], ah1[4], al0[4], al1[4], bh[8], bl[8];
            ldm4(ah0, uAH + aoff0 + koff);
            ldm4(ah1, uAH + aoff1 + koff);
            ldm4(al0, uAL + aoff0 + koff);
            ldm4(al1, uAL + aoff1 + koff);
            ldm4(bh,     uW2H + boff0 + koff);
            ldm4(bh + 4, uW2H + boff1 + koff);
            ldm4(bl,     uW2L + boff0 + koff);
            ldm4(bl + 4, uW2L + boff1 + koff);
            #pragma unroll
            for (int j = 0; j < 4; j++) {
                uint32_t b0h = bh[j*2], b1h = bh[j*2+1];
                uint32_t b0l = bl[j*2], b1l = bl[j*2+1];
                mma16(d[0][j], ah0, b0h, b1h);
                mma16(d[1][j], ah1, b0h, b1h);
                mma16(d[0][j], ah0, b0l, b1l);
                mma16(d[1][j], ah1, b0l, b1l);
                mma16(d[0][j], al0, b0h, b1h);
                mma16(d[1][j], al1, b0h, b1h);
            }
        }
        bar_sync(barid, 256);

        #pragma unroll
        for (int mt = 0; mt < 2; mt++) {
            int er0 = mi * 32 + mt * 16 + g;
            int er1 = er0 + 8;
            int rw0 = sRow[er0], rw1 = sRow[er1];
            #pragma unroll
            for (int j = 0; j < 4; j++) {
                int c = ni * 32 + j * 8 + 2 * tg;
                float m00 = siluf(d[mt][j][0] + sB2[c]);
                float m01 = siluf(d[mt][j][1] + sB2[c + 1]);
                float m10 = siluf(d[mt][j][2] + sB2[c]);
                float m11 = siluf(d[mt][j][3] + sB2[c + 1]);
                asm volatile("red.global.add.v2.f32 [%0], {%1,%2};"
                             :: "l"(g_aggmsg + (size_t)rw0 * Hh + c), "f"(m00), "f"(m01) : "memory");
                asm volatile("red.global.add.v2.f32 [%0], {%1,%2};"
                             :: "l"(g_aggmsg + (size_t)rw1 * Hh + c), "f"(m10), "f"(m11) : "memory");
                uint32_t hi, lo;
                split2(m00, m01, hi, lo);
                AH[er0 * 68 + (c >> 1)] = hi;
                AL[er0 * 68 + (c >> 1)] = lo;
                split2(m10, m11, hi, lo);
                AH[er1 * 68 + (c >> 1)] = hi;
                AL[er1 * 68 + (c >> 1)] = lo;
            }
        }
        bar_sync(barid, 256);

        #pragma unroll
        for (int mt = 0; mt < 2; mt++)
            #pragma unroll
            for (int j = 0; j < 4; j++)
                d[mt][j][0] = d[mt][j][1] = d[mt][j][2] = d[mt][j][3] = 0.f;
        #pragma unroll
        for (int ks = 0; ks < 8; ks++) {
            uint32_t koff = (uint32_t)(ks * 32);
            uint32_t ah0[4], ah1[4], al0[4], al1[4], bh[8], bl[8];
            ldm4(ah0, uAH + aoff0 + koff);
            ldm4(ah1, uAH + aoff1 + koff);
            ldm4(al0, uAL + aoff0 + koff);
            ldm4(al1, uAL + aoff1 + koff);
            ldm4(bh,     uC1H + boff0 + koff);
            ldm4(bh + 4, uC1H + boff1 + koff);
            ldm4(bl,     uC1L + boff0 + koff);
            ldm4(bl + 4, uC1L + boff1 + koff);
            #pragma unroll
            for (int j = 0; j < 4; j++) {
                uint32_t b0h = bh[j*2], b1h = bh[j*2+1];
                uint32_t b0l = bl[j*2], b1l = bl[j*2+1];
                mma16(d[0][j], ah0, b0h, b1h);
                mma16(d[1][j], ah1, b0h, b1h);
                mma16(d[0][j], ah0, b0l, b1l);
                mma16(d[1][j], ah1, b0l, b1l);
                mma16(d[0][j], al0, b0h, b1h);
                mma16(d[1][j], al1, b0h, b1h);
            }
        }

        {
            float prt[2][2];
            prt[0][0] = prt[0][1] = prt[1][0] = prt[1][1] = 0.f;
            #pragma unroll
            for (int mt = 0; mt < 2; mt++) {
                #pragma unroll
                for (int j = 0; j < 4; j++) {
                    int c = ni * 32 + j * 8 + 2 * tg;
                    float c2a = sC2[c], c2b = sC2[c + 1];
                    float u00 = siluf(d[mt][j][0] + sCB[c]);
                    float u01 = siluf(d[mt][j][1] + sCB[c + 1]);
                    float u10 = siluf(d[mt][j][2] + sCB[c]);
                    float u11 = siluf(d[mt][j][3] + sCB[c + 1]);
                    prt[mt][0] += u00 * c2a + u01 * c2b;
                    prt[mt][1] += u10 * c2a + u11 * c2b;
                }
            }
            #pragma unroll
            for (int mt = 0; mt < 2; mt++) {
                #pragma unroll
                for (int rh = 0; rh < 2; rh++) {
                    float pv = prt[mt][rh];
                    pv += __shfl_xor_sync(0xffffffffu, pv, 1);
                    pv += __shfl_xor_sync(0xffffffffu, pv, 2);
                    if (tg == 0)
                        atomicAdd(&sPart[mi * 32 + mt * 16 + rh * 8 + g], pv);
                }
            }
        }
        bar_sync(barid, 256);

        if (gtid < 64) {
            float wsc = tanhf(sPart[gtid]);
            float s = wsc / (sDist[gtid] + EPSf);
            int rw = sRow[gtid];
            atomicAdd(&g_aggtrans[rw * 3 + 0], sDiff[gtid * 3 + 0] * s);
            atomicAdd(&g_aggtrans[rw * 3 + 1], sDiff[gtid * 3 + 1] * s);
            atomicAdd(&g_aggtrans[rw * 3 + 2], sDiff[gtid * 3 + 2] * s);
        }
        bar_sync(barid, 256);
    }
}

// ============ node mma kernel: h_new = h + silu([h|agg]@N1+b1)@N2+b2 =========
// phase1: t = silu(h@N1a + agg@N1b + b1) -> g_TH/g_TL (split bf16)
// phase2: h_new = h + t@N2 + b2 ; x update ; agg zeroing in phase1
__global__ void __launch_bounds__(EDGE_THREADS, 1) node_mma_kernel(
    const float* __restrict__ mask,
    const float* __restrict__ N1w, const float* __restrict__ NB1,
    const float* __restrict__ N2w, const float* __restrict__ NB2,
    int selr, int selw) {
    extern __shared__ float F[];
    uint32_t* U = (uint32_t*)F;
    uint32_t* sBaH = U + O_W2H;   // N1a then N2
    uint32_t* sBaL = U + O_W2L;
    uint32_t* sBbH = U + O_C1H;   // N1b
    uint32_t* sBbL = U + O_C1L;
    float* sB1 = F + O_B1;
    float* sB2 = F + O_B2;

    const float* hc = g_hfeat[selr];
    float* hn = g_hfeat[selw];

    int tid = threadIdx.x;
    int lane = tid & 31, w = tid >> 5;
    int grp = w >> 3;
    int gw = w & 7;
    int gtid = tid & 255;
    int barid = 1 + grp;
    int mi = gw & 1, ni = gw >> 1;
    int g = lane >> 2, tg = lane & 3;

    uint32_t* AH = U + O_A + grp * 8704;
    uint32_t* AL = AH + 4352;
    uint32_t uAH = smem_u32(AH), uAL = smem_u32(AL);
    uint32_t uBaH = smem_u32(sBaH), uBaL = smem_u32(sBaL);
    uint32_t uBbH = smem_u32(sBbH), uBbL = smem_u32(sBbL);
    int l15 = lane & 15;
    uint32_t aoff0 = (uint32_t)(((mi * 32 + l15) * 68 + (lane >> 4) * 4) * 4);
    uint32_t aoff1 = aoff0 + 16 * 68 * 4;
    int bj = (lane >> 4) & 1, bg = (lane >> 3) & 1, b8 = lane & 7;
    uint32_t boff0 = (uint32_t)(((ni * 32 + bj * 8 + b8) * 68 + bg * 4) * 4);
    uint32_t boff1 = boff0 + 16 * 68 * 4;

    // ---- phase 1: stage N1a (rows 0..127) and N1b (rows 128..255) ----
    for (int idx = tid; idx < 64 * 128; idx += EDGE_THREADS) {
        int kp = idx >> 7, n = idx & 127;
        uint32_t hi, lo;
        split2(N1w[(2 * kp) * Hh + n], N1w[(2 * kp + 1) * Hh + n], hi, lo);
        sBaH[n * 68 + kp] = hi;
        sBaL[n * 68 + kp] = lo;
        split2(N1w[(128 + 2 * kp) * Hh + n], N1w[(128 + 2 * kp + 1) * Hh + n], hi, lo);
        sBbH[n * 68 + kp] = hi;
        sBbL[n * 68 + kp] = lo;
    }
    if (tid < Hh) {
        sB1[tid] = NB1[tid];
        sB2[tid] = NB2[tid];
    }
    __syncthreads();

    int tt = blockIdx.x * 2 + grp;
    if (tt < NPQT) {
        int n0 = tt * 64;
        float d[2][4][4];
        #pragma unroll
        for (int mt = 0; mt < 2; mt++)
            #pragma unroll
            for (int j = 0; j < 4; j++)
                d[mt][j][0] = d[mt][j][1] = d[mt][j][2] = d[mt][j][3] = 0.f;

        // pass A: stage h, mma vs N1a
        {
            int jc = lane;
            #pragma unroll
            for (int r = 0; r < 8; r++) {
                int row = gw * 8 + r;
                int node = n0 + row;
                float4 hv = (node < Nn) ? ((const float4*)(hc + (size_t)node * Hh))[jc]
                                        : make_float4(0.f, 0.f, 0.f, 0.f);
                uint32_t h0, l0, h1p, l1;
                split2(hv.x, hv.y, h0, l0);
                split2(hv.z, hv.w, h1p, l1);
                *(uint2*)(AH + row * 68 + 2 * jc) = make_uint2(h0, h1p);
                *(uint2*)(AL + row * 68 + 2 * jc) = make_uint2(l0, l1);
            }
        }
        bar_sync(barid, 256);
        #pragma unroll
        for (int ks = 0; ks < 8; ks++) {
            uint32_t koff = (uint32_t)(ks * 32);
            uint32_t ah0[4], ah1[4], al0[4], al1[4], bh[8], bl[8];
            ldm4(ah0, uAH + aoff0 + koff);
            ldm4(ah1, uAH + aoff1 + koff);
            ldm4(al0, uAL + aoff0 + koff);
            ldm4(al1, uAL + aoff1 + koff);
            ldm4(bh,     uBaH + boff0 + koff);
            ldm4(bh + 4, uBaH + boff1 + koff);
            ldm4(bl,     uBaL + boff0 + koff);
            ldm4(bl + 4, uBaL + boff1 + koff);
            #pragma unroll
            for (int j = 0; j < 4; j++) {
                uint32_t b0h = bh[j*2], b1h = bh[j*2+1];
                uint32_t b0l = bl[j*2], b1l = bl[j*2+1];
                mma16(d[0][j], ah0, b0h, b1h);
                mma16(d[1][j], ah1, b0h, b1h);
                mma16(d[0][j], ah0, b0l, b1l);
                mma16(d[1][j], ah1, b0l, b1l);
                mma16(d[0][j], al0, b0h, b1h);
                mma16(d[1][j], al1, b0h, b1h);
            }
        }
        bar_sync(barid, 256);

        // pass B: stage agg (+ zero agg), mma vs N1b (accumulate)
        {
            int jc = lane;
            #pragma unroll
            for (int r = 0; r < 8; r++) {
                int row = gw * 8 + r;
                int node = n0 + row;
                float4 av = make_float4(0.f, 0.f, 0.f, 0.f);
                if (node < Nn) {
                    float4* ap = (float4*)(g_aggmsg + (size_t)node * Hh) + jc;
                    av = *ap;
                    *ap = make_float4(0.f, 0.f, 0.f, 0.f);
                }
                uint32_t h0, l0, h1p, l1;
                split2(av.x, av.y, h0, l0);
                split2(av.z, av.w, h1p, l1);
                *(uint2*)(AH + row * 68 + 2 * jc) = make_uint2(h0, h1p);
                *(uint2*)(AL + row * 68 + 2 * jc) = make_uint2(l0, l1);
            }
        }
        bar_sync(barid, 256);
        #pragma unroll
        for (int ks = 0; ks < 8; ks++) {
            uint32_t koff = (uint32_t)(ks * 32);
            uint32_t ah0[4], ah1[4], al0[4], al1[4], bh[8], bl[8];
            ldm4(ah0, uAH + aoff0 + koff);
            ldm4(ah1, uAH + aoff1 + koff);
            ldm4(al0, uAL + aoff0 + koff);
            ldm4(al1, uAL + aoff1 + koff);
            ldm4(bh,     uBbH + boff0 + koff);
            ldm4(bh + 4, uBbH + boff1 + koff);
            ldm4(bl,     uBbL + boff0 + koff);
            ldm4(bl + 4, uBbL + boff1 + koff);
            #pragma unroll
            for (int j = 0; j < 4; j++) {
                uint32_t b0h = bh[j*2], b1h = bh[j*2+1];
                uint32_t b0l = bl[j*2], b1l = bl[j*2+1];
                mma16(d[0][j], ah0, b0h, b1h);
                mma16(d[1][j], ah1, b0h, b1h);
                mma16(d[0][j], ah0, b0l, b1l);
                mma16(d[1][j], ah1, b0l, b1l);
                mma16(d[0][j], al0, b0h, b1h);
                mma16(d[1][j], al1, b0h, b1h);
            }
        }

        // epilogue: t = silu(d + b1) -> g_TH/g_TL split
        #pragma unroll
        for (int mt = 0; mt < 2; mt++) {
            int row0 = mi * 32 + mt * 16 + g;
            int row1 = row0 + 8;
            int nd0 = n0 + row0, nd1 = n0 + row1;
            #pragma unroll
            for (int j = 0; j < 4; j++) {
                int c = ni * 32 + j * 8 + 2 * tg;
                float t00 = siluf(d[mt][j][0] + sB1[c]);
                float t01 = siluf(d[mt][j][1] + sB1[c + 1]);
                float t10 = siluf(d[mt][j][2] + sB1[c]);
                float t11 = siluf(d[mt][j][3] + sB1[c + 1]);
                uint32_t hi, lo;
                if (nd0 < Nn) {
                    split2(t00, t01, hi, lo);
                    g_TH[(size_t)nd0 * 64 + (c >> 1)] = hi;
                    g_TL[(size_t)nd0 * 64 + (c >> 1)] = lo;
                }
                if (nd1 < Nn) {
                    split2(t10, t11, hi, lo);
                    g_TH[(size_t)nd1 * 64 + (c >> 1)] = hi;
                    g_TL[(size_t)nd1 * 64 + (c >> 1)] = lo;
                }
            }
        }
    }

    global_bar();

    // ---- phase 2: stage N2, compute h_new = h + t@N2 + b2 ----
    for (int idx = tid; idx < 64 * 128; idx += EDGE_THREADS) {
        int kp = idx >> 7, n = idx & 127;
        uint32_t hi, lo;
        split2(N2w[(2 * kp) * Hh + n], N2w[(2 * kp + 1) * Hh + n], hi, lo);
        sBaH[n * 68 + kp] = hi;
        sBaL[n * 68 + kp] = lo;
    }
    __syncthreads();

    if (tt < NPQT) {
        int n0 = tt * 64;
        // stage A = t from g_TH/g_TL
        {
            int jc = lane;
            #pragma unroll
            for (int r = 0; r < 8; r++) {
                int row = gw * 8 + r;
                int node = n0 + row;
                uint2 hv = make_uint2(0u, 0u), lv = make_uint2(0u, 0u);
                if (node < Nn) {
                    hv = *(const uint2*)(g_TH + (size_t)node * 64 + 2 * jc);
                    lv = *(const uint2*)(g_TL + (size_t)node * 64 + 2 * jc);
                }
                *(uint2*)(AH + row * 68 + 2 * jc) = hv;
                *(uint2*)(AL + row * 68 + 2 * jc) = lv;
            }
        }
        bar_sync(barid, 256);

        float d[2][4][4];
        #pragma unroll
        for (int mt = 0; mt < 2; mt++)
            #pragma unroll
            for (int j = 0; j < 4; j++)
                d[mt][j][0] = d[mt][j][1] = d[mt][j][2] = d[mt][j][3] = 0.f;
        #pragma unroll
        for (int ks = 0; ks < 8; ks++) {
            uint32_t koff = (uint32_t)(ks * 32);
            uint32_t ah0[4], ah1[4], al0[4], al1[4], bh[8], bl[8];
            ldm4(ah0, uAH + aoff0 + koff);
            ldm4(ah1, uAH + aoff1 + koff);
            ldm4(al0, uAL + aoff0 + koff);
            ldm4(al1, uAL + aoff1 + koff);
            ldm4(bh,     uBaH + boff0 + koff);
            ldm4(bh + 4, uBaH + boff1 + koff);
            ldm4(bl,     uBaL + boff0 + koff);
            ldm4(bl + 4, uBaL + boff1 + koff);
            #pragma unroll
            for (int j = 0; j < 4; j++) {
                uint32_t b0h = bh[j*2], b1h = bh[j*2+1];
                uint32_t b0l = bl[j*2], b1l = bl[j*2+1];
                mma16(d[0][j], ah0, b0h, b1h);
                mma16(d[1][j], ah1, b0h, b1h);
                mma16(d[0][j], ah0, b0l, b1l);
                mma16(d[1][j], ah1, b0l, b1l);
                mma16(d[0][j], al0, b0h, b1h);
                mma16(d[1][j], al1, b0h, b1h);
            }
        }

        // epilogue: h_new = hc + d + b2 -> hn
        #pragma unroll
        for (int mt = 0; mt < 2; mt++) {
            int row0 = mi * 32 + mt * 16 + g;
            int row1 = row0 + 8;
            int nd0 = n0 + row0, nd1 = n0 + row1;
            #pragma unroll
            for (int j = 0; j < 4; j++) {
                int c = ni * 32 + j * 8 + 2 * tg;
                if (nd0 < Nn) {
                    float2 hv = *(const float2*)(hc + (size_t)nd0 * Hh + c);
                    *(float2*)(hn + (size_t)nd0 * Hh + c) =
                        make_float2(hv.x + d[mt][j][0] + sB2[c], hv.y + d[mt][j][1] + sB2[c + 1]);
                }
                if (nd1 < Nn) {
                    float2 hv = *(const float2*)(hc + (size_t)nd1 * Hh + c);
                    *(float2*)(hn + (size_t)nd1 * Hh + c) =
                        make_float2(hv.x + d[mt][j][2] + sB2[c], hv.y + d[mt][j][3] + sB2[c + 1]);
                }
            }
        }

        // x update + aggtrans zero
        if (gtid < 64) {
            int node = n0 + gtid;
            if (node < Nn) {
                float mk = mask[node];
                const float* xr = g_x[selr];
                float* xw = g_x[selw];
                float ax = g_aggtrans[node*3+0];
                float ay = g_aggtrans[node*3+1];
                float az = g_aggtrans[node*3+2];
                xw[node*3+0] = xr[node*3+0] + ax * mk;
                xw[node*3+1] = xr[node*3+1] + ay * mk;
                xw[node*3+2] = xr[node*3+2] + az * mk;
                g_aggtrans[node*3+0] = 0.f;
                g_aggtrans[node*3+1] = 0.f;
                g_aggtrans[node*3+2] = 0.f;
            }
        }
    }
}

// ---------------- final ------------------------------------------------------
__global__ void final_kernel(const float* __restrict__ x_in,
                             const float* __restrict__ mask,
                             float* __restrict__ out) {
    int i = blockIdx.x * 256 + threadIdx.x;
    if (i < Nn) {
        float mk = mask[i];
        out[i*3+0] = (g_x[0][i*3+0] - x_in[i*3+0]) * mk;
        out[i*3+1] = (g_x[0][i*3+1] - x_in[i*3+1]) * mk;
        out[i*3+2] = (g_x[0][i*3+2] - x_in[i*3+2]) * mk;
    }
}

// ---------------- launcher ----------------------------------------------------
extern "C" void kernel_launch(void* const* d_in, const int* in_sizes, int n_in,
                              void* d_out, int out_size) {
    const float* h          = (const float*)d_in[0];
    const float* x          = (const float*)d_in[1];
    const int*   edge_index = (const int*)  d_in[2];
    const float* edge_attr  = (const float*)d_in[3];
    const float* t          = (const float*)d_in[4];
    const float* mask       = (const float*)d_in[5];
    const float* time_w1    = (const float*)d_in[6];
    const float* time_b1    = (const float*)d_in[7];
    const float* time_w2    = (const float*)d_in[8];
    const float* time_b2    = (const float*)d_in[9];
    const float* node_emb_w = (const float*)d_in[10];
    const float* node_emb_b = (const float*)d_in[11];
    const float* edge_emb_w = (const float*)d_in[12];
    const float* edge_emb_b = (const float*)d_in[13];
    const float* ew1 = (const float*)d_in[14];
    const float* eb1 = (const float*)d_in[15];
    const float* ew2 = (const float*)d_in[16];
    const float* eb2 = (const float*)d_in[17];
    const float* cw1 = (const float*)d_in[18];
    const float* cb1 = (const float*)d_in[19];
    const float* cw2 = (const float*)d_in[20];
    const float* nw1 = (const float*)d_in[21];
    const float* nb1 = (const float*)d_in[22];
    const float* nw2 = (const float*)d_in[23];
    const float* nb2 = (const float*)d_in[24];
    float* out = (float*)d_out;

    const int* rowi = edge_index;
    const int* coli = edge_index + Ee;

    const int SMEM_EDGE = SMEM_EDGE_WORDS * 4;
    const int SMEM_HF   = 64 * 64 * 4;

    cudaFuncSetAttribute(edge_mma_kernel, cudaFuncAttributeMaxDynamicSharedMemorySize, SMEM_EDGE);
    cudaFuncSetAttribute(node_mma_kernel, cudaFuncAttributeMaxDynamicSharedMemorySize, SMEM_EDGE);

    init_kernel<<<1 + NB_AGG + 4, 256>>>(t, time_w1, time_b1, time_w2, time_b2,
                                         edge_emb_w, edge_emb_b, ew1, eb1);
    emb_kernel<<<NB_HF + NB_CX, 256, SMEM_HF>>>(h, node_emb_w, node_emb_b, x);

    for (int l = 0; l < 4; l++) {
        int sr = l & 1;
        int sw = 1 - sr;
        edge_mma_kernel<<<EDGE_GRID, EDGE_THREADS, SMEM_EDGE>>>(
            rowi, coli, edge_attr, ew1 + (size_t)l * 385 * Hh,
            ew2 + (size_t)l * Hh * Hh, eb2 + l * Hh,
            cw1 + (size_t)l * Hh * Hh, cb1 + l * Hh,
            cw2 + (size_t)l * Hh,
            l);
        node_mma_kernel<<<EDGE_GRID, EDGE_THREADS, SMEM_EDGE>>>(
            mask,
            nw1 + (size_t)l * 256 * Hh, nb1 + l * Hh,
            nw2 + (size_t)l * Hh * Hh,  nb2 + l * Hh,
            sr, sw);
    }

    final_kernel<<<(Nn + 255) / 256, 256>>>(x, mask, out);
}

// round 16
// speedup vs baseline: 1.1193x; 1.0112x over previous
#include <cuda_runtime.h>
#include <cuda_bf16.h>
#include <math.h>
#include <stdint.h>

#define Nn 10000
#define Ee 320000
#define Hh 128
#define EPSf 1e-8f
#define NT64 5000
#define EDGE_GRID 148
#define EDGE_THREADS 512
#define NPQT 157           // 64-node tiles

// ---------------- scratch ----------------------------------------------------
__device__ float g_temb[Hh];
__device__ float g_hfeat[2][Nn * Hh];
__device__ float g_x[2][Nn * 3];
__device__ float g_P[Nn * Hh];
__device__ float g_Q[Nn * Hh];
__device__ float g_CW[4 * 16 * Hh];
__device__ float g_b1eff[4 * Hh];
__device__ float g_aggmsg[Nn * Hh];
__device__ float g_aggtrans[Nn * 3];
__device__ int g_bar_cnt = 0;
__device__ volatile int g_bar_epoch = 0;

__device__ __forceinline__ float siluf(float x) { return x / (1.0f + __expf(-x)); }

__device__ __forceinline__ void mma16(float* d, const uint32_t* a, uint32_t b0, uint32_t b1) {
    asm volatile("mma.sync.aligned.m16n8k16.row.col.f32.bf16.bf16.f32 "
        "{%0,%1,%2,%3}, {%4,%5,%6,%7}, {%8,%9}, {%0,%1,%2,%3};"
        : "+f"(d[0]), "+f"(d[1]), "+f"(d[2]), "+f"(d[3])
        : "r"(a[0]), "r"(a[1]), "r"(a[2]), "r"(a[3]), "r"(b0), "r"(b1));
}

__device__ __forceinline__ void ldm4(uint32_t* r, uint32_t addr) {
    asm volatile("ldmatrix.sync.aligned.m8n8.x4.shared.b16 {%0,%1,%2,%3}, [%4];"
        : "=r"(r[0]), "=r"(r[1]), "=r"(r[2]), "=r"(r[3]) : "r"(addr));
}

__device__ __forceinline__ uint32_t smem_u32(const void* p) {
    uint32_t a;
    asm("{ .reg .u64 t; cvta.to.shared.u64 t, %1; cvt.u32.u64 %0, t; }" : "=r"(a) : "l"(p));
    return a;
}

__device__ __forceinline__ void split2(float x0, float x1, uint32_t& hi, uint32_t& lo) {
    __nv_bfloat162 h = __floats2bfloat162_rn(x0, x1);
    float h0 = __bfloat162float(__low2bfloat16(h));
    float h1 = __bfloat162float(__high2bfloat16(h));
    __nv_bfloat162 l = __floats2bfloat162_rn(x0 - h0, x1 - h1);
    hi = *(uint32_t*)&h;
    lo = *(uint32_t*)&l;
}

__device__ __forceinline__ void bar_sync(int id, int cnt) {
    asm volatile("bar.sync %0, %1;" :: "r"(id), "r"(cnt) : "memory");
}

// epoch-based device-wide barrier (all CTAs resident) — used only in edge PQ
__device__ __forceinline__ void global_bar() {
    __syncthreads();
    if (threadIdx.x == 0) {
        int e = g_bar_epoch;
        __threadfence();
        int v = atomicAdd(&g_bar_cnt, 1);
        if (v == (int)gridDim.x - 1) {
            g_bar_cnt = 0;
            __threadfence();
            g_bar_epoch = e + 1;
        } else {
            while (g_bar_epoch == e) __nanosleep(64);
        }
    }
    __syncthreads();
    __threadfence();
}

// ================= init = temb | zero agg | setup x4 =========================
#define NB_AGG 5118
__global__ void __launch_bounds__(256, 1) init_kernel(
    const float* __restrict__ t,
    const float* __restrict__ w1, const float* __restrict__ b1,
    const float* __restrict__ w2, const float* __restrict__ b2,
    const float* __restrict__ eew, const float* __restrict__ eeb,
    const float* __restrict__ ew1, const float* __restrict__ eb1) {
    int b = blockIdx.x, tid = threadIdx.x;
    if (b == 0) {
        __shared__ float sh[Hh];
        float tv = t[0];
        if (tid < Hh) sh[tid] = siluf(tv * w1[tid] + b1[tid]);
        __syncthreads();
        if (tid < Hh) {
            float acc = b2[tid];
            #pragma unroll 4
            for (int k = 0; k < Hh; k++) acc = fmaf(sh[k], w2[k * Hh + tid], acc);
            g_temb[tid] = acc;
        }
    } else if (b <= NB_AGG) {
        int i = (b - 1) * 256 + tid;
        if (i < Nn * Hh) g_aggmsg[i] = 0.f;
        else if (i < Nn * Hh + Nn * 3) g_aggtrans[i - Nn * Hh] = 0.f;
    } else {
        int L = b - NB_AGG - 1;
        const float* W1 = ew1 + (size_t)L * 385 * Hh;
        const float* B1 = eb1 + L * Hh;
        float* CW = g_CW + L * 16 * Hh;
        float* be = g_b1eff + L * Hh;
        for (int o = tid; o < 16 * Hh; o += 256) {
            int i = o >> 7, j = o & 127;
            float acc = 0.f;
            #pragma unroll 4
            for (int k = 0; k < Hh; k++)
                acc = fmaf(eew[i * Hh + k], W1[(257 + k) * Hh + j], acc);
            CW[o] = acc;
        }
        if (tid < Hh) {
            float acc = B1[tid];
            #pragma unroll 4
            for (int k = 0; k < Hh; k++)
                acc = fmaf(eeb[k], W1[(257 + k) * Hh + tid], acc);
            be[tid] = acc;
        }
    }
}

// ====== emb: hfeat(h@W+b+temb) | copyx =======================================
#define NB_HF 157
#define NB_CX 118
__global__ void __launch_bounds__(256, 1) emb_kernel(
    const float* __restrict__ h, const float* __restrict__ W, const float* __restrict__ B,
    const float* __restrict__ x) {
    int b = blockIdx.x, tid = threadIdx.x;
    if (b < NB_HF) {
        extern __shared__ float sIn[];
        int n0 = b * 64;
        for (int idx = tid; idx < 64 * 64; idx += 256) {
            int i = idx >> 6, k = idx & 63;
            int node = n0 + i;
            sIn[idx] = (node < Nn) ? h[node * 64 + k] : 0.f;
        }
        __syncthreads();
        int jc = tid & 31, wp = tid >> 5;
        float acc[8][4];
        #pragma unroll
        for (int r = 0; r < 8; r++) { acc[r][0]=acc[r][1]=acc[r][2]=acc[r][3]=0.f; }
        const float4* Wv = (const float4*)W;
        for (int k = 0; k < 64; k++) {
            float4 w = Wv[k * 32 + jc];
            #pragma unroll
            for (int r = 0; r < 8; r++) {
                float a = sIn[(wp * 8 + r) * 64 + k];
                acc[r][0]=fmaf(a,w.x,acc[r][0]); acc[r][1]=fmaf(a,w.y,acc[r][1]);
                acc[r][2]=fmaf(a,w.z,acc[r][2]); acc[r][3]=fmaf(a,w.w,acc[r][3]);
            }
        }
        float4 bv = ((const float4*)B)[jc];
        float4 tv = ((const float4*)g_temb)[jc];
        #pragma unroll
        for (int r = 0; r < 8; r++) {
            int node = n0 + wp * 8 + r;
            if (node < Nn) {
                float4 o;
                o.x = acc[r][0]+bv.x+tv.x; o.y = acc[r][1]+bv.y+tv.y;
                o.z = acc[r][2]+bv.z+tv.z; o.w = acc[r][3]+bv.w+tv.w;
                ((float4*)(g_hfeat[0] + node * Hh))[jc] = o;
            }
        }
    } else {
        int i = (b - NB_HF) * 256 + tid;
        if (i < Nn * 3) g_x[0][i] = x[i];
    }
}

// ============ edge kernel: PQ mma pre-phase + dual-pipeline edge tiles =======
#define O_W2H  0
#define O_W2L  8704
#define O_C1H  17408
#define O_C1L  26112
#define O_A    34816
#define O_EA   52224
#define O_CW   54272
#define O_WD   56320
#define O_B1   56448
#define O_B2   56576
#define O_CB   56704
#define O_C2   56832
#define O_GEO  56960
#define SMEM_EDGE_WORDS 57984

__global__ void __launch_bounds__(EDGE_THREADS, 1) edge_mma_kernel(
    const int* __restrict__ rowi, const int* __restrict__ coli,
    const float* __restrict__ ea,
    const float* __restrict__ W1,
    const float* __restrict__ W2g, const float* __restrict__ B2,
    const float* __restrict__ C1g, const float* __restrict__ CB,
    const float* __restrict__ C2, int l) {
    extern __shared__ float F[];
    uint32_t* U = (uint32_t*)F;
    uint32_t* sW2H = U + O_W2H;
    uint32_t* sW2L = U + O_W2L;
    uint32_t* sC1H = U + O_C1H;
    uint32_t* sC1L = U + O_C1L;
    float* sCW = F + O_CW;
    float* sWd = F + O_WD;
    float* sB1 = F + O_B1;
    float* sB2 = F + O_B2;
    float* sCB = F + O_CB;
    float* sC2 = F + O_C2;

    int tid = threadIdx.x;
    int lane = tid & 31, w = tid >> 5;
    int sel = l & 1;

    const float* xc = g_x[sel];
    const float* hf = g_hfeat[sel];

    int grp = w >> 3;
    int gw = w & 7;
    int gtid = tid & 255;
    int barid = 1 + grp;
    int mi = gw & 1, ni = gw >> 1;
    int g = lane >> 2, tg = lane & 3;

    uint32_t* AH = U + O_A + grp * 8704;
    uint32_t* AL = AH + 4352;
    float* sEA  = F + O_EA + grp * 1024;
    float* GEO  = F + O_GEO + grp * 512;
    int*   sRow = (int*)GEO;
    int*   sCol = (int*)(GEO + 64);
    float* sD2v = GEO + 128;
    float* sDist= GEO + 192;
    float* sPart= GEO + 256;
    float* sDiff= GEO + 320;

    uint32_t uAH = smem_u32(AH), uAL = smem_u32(AL);
    uint32_t uW2H = smem_u32(sW2H), uW2L = smem_u32(sW2L);
    uint32_t uC1H = smem_u32(sC1H), uC1L = smem_u32(sC1L);
    int l15 = lane & 15;
    uint32_t aoff0 = (uint32_t)(((mi * 32 + l15) * 68 + (lane >> 4) * 4) * 4);
    uint32_t aoff1 = aoff0 + 16 * 68 * 4;
    int bj = (lane >> 4) & 1, bg = (lane >> 3) & 1, b8 = lane & 7;
    uint32_t boff0 = (uint32_t)(((ni * 32 + bj * 8 + b8) * 68 + bg * 4) * 4);
    uint32_t boff1 = boff0 + 16 * 68 * 4;

    // ---- PQ pre-phase: P = hf@W1a, Q = hf@W1b ----
    for (int idx = tid; idx < 64 * 128; idx += EDGE_THREADS) {
        int kp = idx >> 7, n = idx & 127;
        uint32_t hi, lo;
        split2(W1[(2 * kp) * Hh + n], W1[(2 * kp + 1) * Hh + n], hi, lo);
        sW2H[n * 68 + kp] = hi;
        sW2L[n * 68 + kp] = lo;
        split2(W1[(128 + 2 * kp) * Hh + n], W1[(128 + 2 * kp + 1) * Hh + n], hi, lo);
        sC1H[n * 68 + kp] = hi;
        sC1L[n * 68 + kp] = lo;
    }
    __syncthreads();

    {
        int tt = blockIdx.x * 2 + grp;
        if (tt < NPQT) {
            int n0 = tt * 64;
            {
                int jc = lane;
                #pragma unroll
                for (int r = 0; r < 8; r++) {
                    int row = gw * 8 + r;
                    int node = n0 + row;
                    float4 hv = (node < Nn) ? ((const float4*)(hf + (size_t)node * Hh))[jc]
                                            : make_float4(0.f, 0.f, 0.f, 0.f);
                    uint32_t h0, l0, h1p, l1;
                    split2(hv.x, hv.y, h0, l0);
                    split2(hv.z, hv.w, h1p, l1);
                    *(uint2*)(AH + row * 68 + 2 * jc) = make_uint2(h0, h1p);
                    *(uint2*)(AL + row * 68 + 2 * jc) = make_uint2(l0, l1);
                }
            }
            bar_sync(barid, 256);

            float d[2][4][4];
            #pragma unroll
            for (int pass = 0; pass < 2; pass++) {
                uint32_t uBH = pass ? uC1H : uW2H;
                uint32_t uBL = pass ? uC1L : uW2L;
                float* dstG = pass ? g_Q : g_P;
                #pragma unroll
                for (int mt = 0; mt < 2; mt++)
                    #pragma unroll
                    for (int j = 0; j < 4; j++)
                        d[mt][j][0] = d[mt][j][1] = d[mt][j][2] = d[mt][j][3] = 0.f;
                #pragma unroll
                for (int ks = 0; ks < 8; ks++) {
                    uint32_t koff = (uint32_t)(ks * 32);
                    uint32_t ah0[4], ah1[4], al0[4], al1[4], bh[8], bl[8];
                    ldm4(ah0, uAH + aoff0 + koff);
                    ldm4(ah1, uAH + aoff1 + koff);
                    ldm4(al0, uAL + aoff0 + koff);
                    ldm4(al1, uAL + aoff1 + koff);
                    ldm4(bh,     uBH + boff0 + koff);
                    ldm4(bh + 4, uBH + boff1 + koff);
                    ldm4(bl,     uBL + boff0 + koff);
                    ldm4(bl + 4, uBL + boff1 + koff);
                    #pragma unroll
                    for (int j = 0; j < 4; j++) {
                        uint32_t b0h = bh[j*2], b1h = bh[j*2+1];
                        uint32_t b0l = bl[j*2], b1l = bl[j*2+1];
                        mma16(d[0][j], ah0, b0h, b1h);
                        mma16(d[1][j], ah1, b0h, b1h);
                        mma16(d[0][j], ah0, b0l, b1l);
                        mma16(d[1][j], ah1, b0l, b1l);
                        mma16(d[0][j], al0, b0h, b1h);
                        mma16(d[1][j], al1, b0h, b1h);
                    }
                }
                #pragma unroll
                for (int mt = 0; mt < 2; mt++) {
                    int row0 = mi * 32 + mt * 16 + g;
                    int row1 = row0 + 8;
                    int nd0 = n0 + row0, nd1 = n0 + row1;
                    #pragma unroll
                    for (int j = 0; j < 4; j++) {
                        int c = ni * 32 + j * 8 + 2 * tg;
                        if (nd0 < Nn)
                            *(float2*)(dstG + (size_t)nd0 * Hh + c) = make_float2(d[mt][j][0], d[mt][j][1]);
                        if (nd1 < Nn)
                            *(float2*)(dstG + (size_t)nd1 * Hh + c) = make_float2(d[mt][j][2], d[mt][j][3]);
                    }
                }
            }
        }
    }

    global_bar();

    // ---- stage real edge weights ----
    for (int idx = tid; idx < 64 * 128; idx += EDGE_THREADS) {
        int kp = idx >> 7, n = idx & 127;
        uint32_t hi, lo;
        split2(W2g[(2 * kp) * 128 + n], W2g[(2 * kp + 1) * 128 + n], hi, lo);
        sW2H[n * 68 + kp] = hi;
        sW2L[n * 68 + kp] = lo;
        split2(C1g[(2 * kp) * 128 + n], C1g[(2 * kp + 1) * 128 + n], hi, lo);
        sC1H[n * 68 + kp] = hi;
        sC1L[n * 68 + kp] = lo;
    }
    {
        const float* CWl = g_CW + l * 16 * Hh;
        for (int idx = tid; idx < 16 * Hh; idx += EDGE_THREADS) sCW[idx] = CWl[idx];
    }
    if (tid < Hh) {
        sWd[tid] = W1[256 * Hh + tid];
        sB1[tid] = g_b1eff[l * Hh + tid];
        sB2[tid] = B2[tid];
        sCB[tid] = CB[tid];
        sC2[tid] = C2[tid];
    }
    __syncthreads();

    int stride = gridDim.x * 2;
    int tile0 = blockIdx.x * 2 + grp;

    int pf_r = 0, pf_c = 0;
    float4 pf_ea = make_float4(0.f, 0.f, 0.f, 0.f);
    if (tile0 < NT64) {
        int e0 = tile0 * 64;
        if (gtid < 64) { pf_r = rowi[e0 + gtid]; pf_c = coli[e0 + gtid]; }
        pf_ea = ((const float4*)(ea + (size_t)(e0 + (gtid >> 2)) * 16))[gtid & 3];
    }

    for (int tile = tile0; tile < NT64; tile += stride) {
        if (gtid < 64) {
            int r = pf_r, c = pf_c;
            sRow[gtid] = r; sCol[gtid] = c;
            float dx = xc[r*3+0] - xc[c*3+0];
            float dy = xc[r*3+1] - xc[c*3+1];
            float dz = xc[r*3+2] - xc[c*3+2];
            float d2 = dx*dx + dy*dy + dz*dz;
            sDiff[gtid*3+0] = dx; sDiff[gtid*3+1] = dy; sDiff[gtid*3+2] = dz;
            sD2v[gtid] = d2;
            sDist[gtid] = sqrtf(d2 + EPSf);
            sPart[gtid] = 0.f;
        }
        {
            int e = gtid >> 2, q = gtid & 3;
            float* dst = sEA + e * 16 + q * 4;
            dst[0] = pf_ea.x; dst[1] = pf_ea.y; dst[2] = pf_ea.z; dst[3] = pf_ea.w;
        }
        bar_sync(barid, 256);

        {
            int tn = tile + stride;
            if (tn < NT64) {
                int e0n = tn * 64;
                if (gtid < 64) { pf_r = rowi[e0n + gtid]; pf_c = coli[e0n + gtid]; }
                pf_ea = ((const float4*)(ea + (size_t)(e0n + (gtid >> 2)) * 16))[gtid & 3];
            }
        }

        {
            int jc = lane;
            float acc[8][4];
            float4 wd = ((const float4*)sWd)[jc];
            float4 b1 = ((const float4*)sB1)[jc];
            #pragma unroll
            for (int r = 0; r < 8; r++) {
                int e = gw * 8 + r;
                int rw = sRow[e], cl = sCol[e];
                float d2 = sD2v[e];
                float4 pp = ((const float4*)(g_P + (size_t)rw * Hh))[jc];
                float4 qq = ((const float4*)(g_Q + (size_t)cl * Hh))[jc];
                acc[r][0] = pp.x + qq.x + fmaf(d2, wd.x, b1.x);
                acc[r][1] = pp.y + qq.y + fmaf(d2, wd.y, b1.y);
                acc[r][2] = pp.z + qq.z + fmaf(d2, wd.z, b1.z);
                acc[r][3] = pp.w + qq.w + fmaf(d2, wd.w, b1.w);
            }
            const float4* CW4 = (const float4*)sCW;
            #pragma unroll
            for (int k = 0; k < 16; k++) {
                float4 cw = CW4[k * 32 + jc];
                #pragma unroll
                for (int r = 0; r < 8; r++) {
                    float a = sEA[(gw * 8 + r) * 16 + k];
                    acc[r][0] = fmaf(a, cw.x, acc[r][0]);
                    acc[r][1] = fmaf(a, cw.y, acc[r][1]);
                    acc[r][2] = fmaf(a, cw.z, acc[r][2]);
                    acc[r][3] = fmaf(a, cw.w, acc[r][3]);
                }
            }
            #pragma unroll
            for (int r = 0; r < 8; r++) {
                int e = gw * 8 + r;
                float s0 = siluf(acc[r][0]), s1 = siluf(acc[r][1]);
                float s2 = siluf(acc[r][2]), s3 = siluf(acc[r][3]);
                uint32_t h0, l0, h1p, l1;
                split2(s0, s1, h0, l0);
                split2(s2, s3, h1p, l1);
                *(uint2*)(AH + e * 68 + 2 * jc) = make_uint2(h0, h1p);
                *(uint2*)(AL + e * 68 + 2 * jc) = make_uint2(l0, l1);
            }
        }
        bar_sync(barid, 256);

        float d[2][4][4];

        #pragma unroll
        for (int mt = 0; mt < 2; mt++)
            #pragma unroll
            for (int j = 0; j < 4; j++)
                d[mt][j][0] = d[mt][j][1] = d[mt][j][2] = d[mt][j][3] = 0.f;
        #pragma unroll
        for (int ks = 0; ks < 8; ks++) {
            uint32_t koff = (uint32_t)(ks * 32);
            uint32_t ah0[4], ah1[4], al0[4], al1[4], bh[8], bl[8];
            ldm4(ah0, uAH + aoff0 + koff);
            ldm4(ah1, uAH + aoff1 + koff);
            ldm4(al0, uAL + aoff0 + koff);
            ldm4(al1, uAL + aoff1 + koff);
            ldm4(bh,     uW2H + boff0 + koff);
            ldm4(bh + 4, uW2H + boff1 + koff);
            ldm4(bl,     uW2L + boff0 + koff);
            ldm4(bl + 4, uW2L + boff1 + koff);
            #pragma unroll
            for (int j = 0; j < 4; j++) {
                uint32_t b0h = bh[j*2], b1h = bh[j*2+1];
                uint32_t b0l = bl[j*2], b1l = bl[j*2+1];
                mma16(d[0][j], ah0, b0h, b1h);
                mma16(d[1][j], ah1, b0h, b1h);
                mma16(d[0][j], ah0, b0l, b1l);
                mma16(d[1][j], ah1, b0l, b1l);
                mma16(d[0][j], al0, b0h, b1h);
                mma16(d[1][j], al1, b0h, b1h);
            }
        }
        bar_sync(barid, 256);

        #pragma unroll
        for (int mt = 0; mt < 2; mt++) {
            int er0 = mi * 32 + mt * 16 + g;
            int er1 = er0 + 8;
            int rw0 = sRow[er0], rw1 = sRow[er1];
            #pragma unroll
            for (int j = 0; j < 4; j++) {
                int c = ni * 32 + j * 8 + 2 * tg;
                float m00 = siluf(d[mt][j][0] + sB2[c]);
                float m01 = siluf(d[mt][j][1] + sB2[c + 1]);
                float m10 = siluf(d[mt][j][2] + sB2[c]);
                float m11 = siluf(d[mt][j][3] + sB2[c + 1]);
                asm volatile("red.global.add.v2.f32 [%0], {%1,%2};"
                             :: "l"(g_aggmsg + (size_t)rw0 * Hh + c), "f"(m00), "f"(m01) : "memory");
                asm volatile("red.global.add.v2.f32 [%0], {%1,%2};"
                             :: "l"(g_aggmsg + (size_t)rw1 * Hh + c), "f"(m10), "f"(m11) : "memory");
                uint32_t hi, lo;
                split2(m00, m01, hi, lo);
                AH[er0 * 68 + (c >> 1)] = hi;
                AL[er0 * 68 + (c >> 1)] = lo;
                split2(m10, m11, hi, lo);
                AH[er1 * 68 + (c >> 1)] = hi;
                AL[er1 * 68 + (c >> 1)] = lo;
            }
        }
        bar_sync(barid, 256);

        #pragma unroll
        for (int mt = 0; mt < 2; mt++)
            #pragma unroll
            for (int j = 0; j < 4; j++)
                d[mt][j][0] = d[mt][j][1] = d[mt][j][2] = d[mt][j][3] = 0.f;
        #pragma unroll
        for (int ks = 0; ks < 8; ks++) {
            uint32_t koff = (uint32_t)(ks * 32);
            uint32_t ah0[4], ah1[4], al0[4], al1[4], bh[8], bl[8];
            ldm4(ah0, uAH + aoff0 + koff);
            ldm4(ah1, uAH + aoff1 + koff);
            ldm4(al0, uAL + aoff0 + koff);
            ldm4(al1, uAL + aoff1 + koff);
            ldm4(bh,     uC1H + boff0 + koff);
            ldm4(bh + 4, uC1H + boff1 + koff);
            ldm4(bl,     uC1L + boff0 + koff);
            ldm4(bl + 4, uC1L + boff1 + koff);
            #pragma unroll
            for (int j = 0; j < 4; j++) {
                uint32_t b0h = bh[j*2], b1h = bh[j*2+1];
                uint32_t b0l = bl[j*2], b1l = bl[j*2+1];
                mma16(d[0][j], ah0, b0h, b1h);
                mma16(d[1][j], ah1, b0h, b1h);
                mma16(d[0][j], ah0, b0l, b1l);
                mma16(d[1][j], ah1, b0l, b1l);
                mma16(d[0][j], al0, b0h, b1h);
                mma16(d[1][j], al1, b0h, b1h);
            }
        }

        {
            float prt[2][2];
            prt[0][0] = prt[0][1] = prt[1][0] = prt[1][1] = 0.f;
            #pragma unroll
            for (int mt = 0; mt < 2; mt++) {
                #pragma unroll
                for (int j = 0; j < 4; j++) {
                    int c = ni * 32 + j * 8 + 2 * tg;
                    float c2a = sC2[c], c2b = sC2[c + 1];
                    float u00 = siluf(d[mt][j][0] + sCB[c]);
                    float u01 = siluf(d[mt][j][1] + sCB[c + 1]);
                    float u10 = siluf(d[mt][j][2] + sCB[c]);
                    float u11 = siluf(d[mt][j][3] + sCB[c + 1]);
                    prt[mt][0] += u00 * c2a + u01 * c2b;
                    prt[mt][1] += u10 * c2a + u11 * c2b;
                }
            }
            #pragma unroll
            for (int mt = 0; mt < 2; mt++) {
                #pragma unroll
                for (int rh = 0; rh < 2; rh++) {
                    float pv = prt[mt][rh];
                    pv += __shfl_xor_sync(0xffffffffu, pv, 1);
                    pv += __shfl_xor_sync(0xffffffffu, pv, 2);
                    if (tg == 0)
                        atomicAdd(&sPart[mi * 32 + mt * 16 + rh * 8 + g], pv);
                }
            }
        }
        bar_sync(barid, 256);

        if (gtid < 64) {
            float wsc = tanhf(sPart[gtid]);
            float s = wsc / (sDist[gtid] + EPSf);
            int rw = sRow[gtid];
            atomicAdd(&g_aggtrans[rw * 3 + 0], sDiff[gtid * 3 + 0] * s);
            atomicAdd(&g_aggtrans[rw * 3 + 1], sDiff[gtid * 3 + 1] * s);
            atomicAdd(&g_aggtrans[rw * 3 + 2], sDiff[gtid * 3 + 2] * s);
        }
        bar_sync(barid, 256);
    }
}

// ============ node mma kernel (CTA-local; no global barrier) =================
// phase1: t = silu(h@N1a + agg@N1b + b1) -> kept split in group's AH/AL smem
// phase2: re-stage N2; h_new = h + t@N2 + b2 ; x update ; agg zeroed in pass B
__global__ void __launch_bounds__(EDGE_THREADS, 1) node_mma_kernel(
    const float* __restrict__ mask,
    const float* __restrict__ N1w, const float* __restrict__ NB1,
    const float* __restrict__ N2w, const float* __restrict__ NB2,
    int selr, int selw) {
    extern __shared__ float F[];
    uint32_t* U = (uint32_t*)F;
    uint32_t* sBaH = U + O_W2H;   // N1a then N2
    uint32_t* sBaL = U + O_W2L;
    uint32_t* sBbH = U + O_C1H;   // N1b
    uint32_t* sBbL = U + O_C1L;
    float* sB1 = F + O_B1;
    float* sB2 = F + O_B2;

    const float* hc = g_hfeat[selr];
    float* hn = g_hfeat[selw];

    int tid = threadIdx.x;
    int lane = tid & 31, w = tid >> 5;
    int grp = w >> 3;
    int gw = w & 7;
    int gtid = tid & 255;
    int barid = 1 + grp;
    int mi = gw & 1, ni = gw >> 1;
    int g = lane >> 2, tg = lane & 3;

    uint32_t* AH = U + O_A + grp * 8704;
    uint32_t* AL = AH + 4352;
    uint32_t uAH = smem_u32(AH), uAL = smem_u32(AL);
    uint32_t uBaH = smem_u32(sBaH), uBaL = smem_u32(sBaL);
    uint32_t uBbH = smem_u32(sBbH), uBbL = smem_u32(sBbL);
    int l15 = lane & 15;
    uint32_t aoff0 = (uint32_t)(((mi * 32 + l15) * 68 + (lane >> 4) * 4) * 4);
    uint32_t aoff1 = aoff0 + 16 * 68 * 4;
    int bj = (lane >> 4) & 1, bg = (lane >> 3) & 1, b8 = lane & 7;
    uint32_t boff0 = (uint32_t)(((ni * 32 + bj * 8 + b8) * 68 + bg * 4) * 4);
    uint32_t boff1 = boff0 + 16 * 68 * 4;

    // ---- stage N1a and N1b ----
    for (int idx = tid; idx < 64 * 128; idx += EDGE_THREADS) {
        int kp = idx >> 7, n = idx & 127;
        uint32_t hi, lo;
        split2(N1w[(2 * kp) * Hh + n], N1w[(2 * kp + 1) * Hh + n], hi, lo);
        sBaH[n * 68 + kp] = hi;
        sBaL[n * 68 + kp] = lo;
        split2(N1w[(128 + 2 * kp) * Hh + n], N1w[(128 + 2 * kp + 1) * Hh + n], hi, lo);
        sBbH[n * 68 + kp] = hi;
        sBbL[n * 68 + kp] = lo;
    }
    if (tid < Hh) {
        sB1[tid] = NB1[tid];
        sB2[tid] = NB2[tid];
    }
    __syncthreads();

    int tt = blockIdx.x * 2 + grp;
    float d[2][4][4];

    if (tt < NPQT) {
        int n0 = tt * 64;
        #pragma unroll
        for (int mt = 0; mt < 2; mt++)
            #pragma unroll
            for (int j = 0; j < 4; j++)
                d[mt][j][0] = d[mt][j][1] = d[mt][j][2] = d[mt][j][3] = 0.f;

        // pass A: stage h, mma vs N1a
        {
            int jc = lane;
            #pragma unroll
            for (int r = 0; r < 8; r++) {
                int row = gw * 8 + r;
                int node = n0 + row;
                float4 hv = (node < Nn) ? ((const float4*)(hc + (size_t)node * Hh))[jc]
                                        : make_float4(0.f, 0.f, 0.f, 0.f);
                uint32_t h0, l0, h1p, l1;
                split2(hv.x, hv.y, h0, l0);
                split2(hv.z, hv.w, h1p, l1);
                *(uint2*)(AH + row * 68 + 2 * jc) = make_uint2(h0, h1p);
                *(uint2*)(AL + row * 68 + 2 * jc) = make_uint2(l0, l1);
            }
        }
        bar_sync(barid, 256);
        #pragma unroll
        for (int ks = 0; ks < 8; ks++) {
            uint32_t koff = (uint32_t)(ks * 32);
            uint32_t ah0[4], ah1[4], al0[4], al1[4], bh[8], bl[8];
            ldm4(ah0, uAH + aoff0 + koff);
            ldm4(ah1, uAH + aoff1 + koff);
            ldm4(al0, uAL + aoff0 + koff);
            ldm4(al1, uAL + aoff1 + koff);
            ldm4(bh,     uBaH + boff0 + koff);
            ldm4(bh + 4, uBaH + boff1 + koff);
            ldm4(bl,     uBaL + boff0 + koff);
            ldm4(bl + 4, uBaL + boff1 + koff);
            #pragma unroll
            for (int j = 0; j < 4; j++) {
                uint32_t b0h = bh[j*2], b1h = bh[j*2+1];
                uint32_t b0l = bl[j*2], b1l = bl[j*2+1];
                mma16(d[0][j], ah0, b0h, b1h);
                mma16(d[1][j], ah1, b0h, b1h);
                mma16(d[0][j], ah0, b0l, b1l);
                mma16(d[1][j], ah1, b0l, b1l);
                mma16(d[0][j], al0, b0h, b1h);
                mma16(d[1][j], al1, b0h, b1h);
            }
        }
        bar_sync(barid, 256);

        // pass B: stage agg (+ zero agg), mma vs N1b (accumulate)
        {
            int jc = lane;
            #pragma unroll
            for (int r = 0; r < 8; r++) {
                int row = gw * 8 + r;
                int node = n0 + row;
                float4 av = make_float4(0.f, 0.f, 0.f, 0.f);
                if (node < Nn) {
                    float4* ap = (float4*)(g_aggmsg + (size_t)node * Hh) + jc;
                    av = *ap;
                    *ap = make_float4(0.f, 0.f, 0.f, 0.f);
                }
                uint32_t h0, l0, h1p, l1;
                split2(av.x, av.y, h0, l0);
                split2(av.z, av.w, h1p, l1);
                *(uint2*)(AH + row * 68 + 2 * jc) = make_uint2(h0, h1p);
                *(uint2*)(AL + row * 68 + 2 * jc) = make_uint2(l0, l1);
            }
        }
        bar_sync(barid, 256);
        #pragma unroll
        for (int ks = 0; ks < 8; ks++) {
            uint32_t koff = (uint32_t)(ks * 32);
            uint32_t ah0[4], ah1[4], al0[4], al1[4], bh[8], bl[8];
            ldm4(ah0, uAH + aoff0 + koff);
            ldm4(ah1, uAH + aoff1 + koff);
            ldm4(al0, uAL + aoff0 + koff);
            ldm4(al1, uAL + aoff1 + koff);
            ldm4(bh,     uBbH + boff0 + koff);
            ldm4(bh + 4, uBbH + boff1 + koff);
            ldm4(bl,     uBbL + boff0 + koff);
            ldm4(bl + 4, uBbL + boff1 + koff);
            #pragma unroll
            for (int j = 0; j < 4; j++) {
                uint32_t b0h = bh[j*2], b1h = bh[j*2+1];
                uint32_t b0l = bl[j*2], b1l = bl[j*2+1];
                mma16(d[0][j], ah0, b0h, b1h);
                mma16(d[1][j], ah1, b0h, b1h);
                mma16(d[0][j], ah0, b0l, b1l);
                mma16(d[1][j], ah1, b0l, b1l);
                mma16(d[0][j], al0, b0h, b1h);
                mma16(d[1][j], al1, b0h, b1h);
            }
        }
        bar_sync(barid, 256);   // all group warps done reading agg tile

        // epilogue: t = silu(d + b1) -> split, kept in group's AH/AL
        #pragma unroll
        for (int mt = 0; mt < 2; mt++) {
            int er0 = mi * 32 + mt * 16 + g;
            int er1 = er0 + 8;
            #pragma unroll
            for (int j = 0; j < 4; j++) {
                int c = ni * 32 + j * 8 + 2 * tg;
                float t00 = siluf(d[mt][j][0] + sB1[c]);
                float t01 = siluf(d[mt][j][1] + sB1[c + 1]);
                float t10 = siluf(d[mt][j][2] + sB1[c]);
                float t11 = siluf(d[mt][j][3] + sB1[c + 1]);
                uint32_t hi, lo;
                split2(t00, t01, hi, lo);
                AH[er0 * 68 + (c >> 1)] = hi;
                AL[er0 * 68 + (c >> 1)] = lo;
                split2(t10, t11, hi, lo);
                AH[er1 * 68 + (c >> 1)] = hi;
                AL[er1 * 68 + (c >> 1)] = lo;
            }
        }
    }

    // ---- re-stage N2 over N1a slot (CTA-wide) ----
    __syncthreads();
    for (int idx = tid; idx < 64 * 128; idx += EDGE_THREADS) {
        int kp = idx >> 7, n = idx & 127;
        uint32_t hi, lo;
        split2(N2w[(2 * kp) * Hh + n], N2w[(2 * kp + 1) * Hh + n], hi, lo);
        sBaH[n * 68 + kp] = hi;
        sBaL[n * 68 + kp] = lo;
    }
    __syncthreads();

    if (tt < NPQT) {
        int n0 = tt * 64;
        #pragma unroll
        for (int mt = 0; mt < 2; mt++)
            #pragma unroll
            for (int j = 0; j < 4; j++)
                d[mt][j][0] = d[mt][j][1] = d[mt][j][2] = d[mt][j][3] = 0.f;
        #pragma unroll
        for (int ks = 0; ks < 8; ks++) {
            uint32_t koff = (uint32_t)(ks * 32);
            uint32_t ah0[4], ah1[4], al0[4], al1[4], bh[8], bl[8];
            ldm4(ah0, uAH + aoff0 + koff);
            ldm4(ah1, uAH + aoff1 + koff);
            ldm4(al0, uAL + aoff0 + koff);
            ldm4(al1, uAL + aoff1 + koff);
            ldm4(bh,     uBaH + boff0 + koff);
            ldm4(bh + 4, uBaH + boff1 + koff);
            ldm4(bl,     uBaL + boff0 + koff);
            ldm4(bl + 4, uBaL + boff1 + koff);
            #pragma unroll
            for (int j = 0; j < 4; j++) {
                uint32_t b0h = bh[j*2], b1h = bh[j*2+1];
                uint32_t b0l = bl[j*2], b1l = bl[j*2+1];
                mma16(d[0][j], ah0, b0h, b1h);
                mma16(d[1][j], ah1, b0h, b1h);
                mma16(d[0][j], ah0, b0l, b1l);
                mma16(d[1][j], ah1, b0l, b1l);
                mma16(d[0][j], al0, b0h, b1h);
                mma16(d[1][j], al1, b0h, b1h);
            }
        }

        // epilogue: h_new = hc + d + b2 -> hn
        #pragma unroll
        for (int mt = 0; mt < 2; mt++) {
            int row0 = mi * 32 + mt * 16 + g;
            int row1 = row0 + 8;
            int nd0 = n0 + row0, nd1 = n0 + row1;
            #pragma unroll
            for (int j = 0; j < 4; j++) {
                int c = ni * 32 + j * 8 + 2 * tg;
                if (nd0 < Nn) {
                    float2 hv = *(const float2*)(hc + (size_t)nd0 * Hh + c);
                    *(float2*)(hn + (size_t)nd0 * Hh + c) =
                        make_float2(hv.x + d[mt][j][0] + sB2[c], hv.y + d[mt][j][1] + sB2[c + 1]);
                }
                if (nd1 < Nn) {
                    float2 hv = *(const float2*)(hc + (size_t)nd1 * Hh + c);
                    *(float2*)(hn + (size_t)nd1 * Hh + c) =
                        make_float2(hv.x + d[mt][j][2] + sB2[c], hv.y + d[mt][j][3] + sB2[c + 1]);
                }
            }
        }

        // x update + aggtrans zero
        if (gtid < 64) {
            int node = n0 + gtid;
            if (node < Nn) {
                float mk = mask[node];
                const float* xr = g_x[selr];
                float* xw = g_x[selw];
                float ax = g_aggtrans[node*3+0];
                float ay = g_aggtrans[node*3+1];
                float az = g_aggtrans[node*3+2];
                xw[node*3+0] = xr[node*3+0] + ax * mk;
                xw[node*3+1] = xr[node*3+1] + ay * mk;
                xw[node*3+2] = xr[node*3+2] + az * mk;
                g_aggtrans[node*3+0] = 0.f;
                g_aggtrans[node*3+1] = 0.f;
                g_aggtrans[node*3+2] = 0.f;
            }
        }
    }
}

// ---------------- final ------------------------------------------------------
__global__ void final_kernel(const float* __restrict__ x_in,
                             const float* __restrict__ mask,
                             float* __restrict__ out) {
    int i = blockIdx.x * 256 + threadIdx.x;
    if (i < Nn) {
        float mk = mask[i];
        out[i*3+0] = (g_x[0][i*3+0] - x_in[i*3+0]) * mk;
        out[i*3+1] = (g_x[0][i*3+1] - x_in[i*3+1]) * mk;
        out[i*3+2] = (g_x[0][i*3+2] - x_in[i*3+2]) * mk;
    }
}

// ---------------- launcher ----------------------------------------------------
extern "C" void kernel_launch(void* const* d_in, const int* in_sizes, int n_in,
                              void* d_out, int out_size) {
    const float* h          = (const float*)d_in[0];
    const float* x          = (const float*)d_in[1];
    const int*   edge_index = (const int*)  d_in[2];
    const float* edge_attr  = (const float*)d_in[3];
    const float* t          = (const float*)d_in[4];
    const float* mask       = (const float*)d_in[5];
    const float* time_w1    = (const float*)d_in[6];
    const float* time_b1    = (const float*)d_in[7];
    const float* time_w2    = (const float*)d_in[8];
    const float* time_b2    = (const float*)d_in[9];
    const float* node_emb_w = (const float*)d_in[10];
    const float* node_emb_b = (const float*)d_in[11];
    const float* edge_emb_w = (const float*)d_in[12];
    const float* edge_emb_b = (const float*)d_in[13];
    const float* ew1 = (const float*)d_in[14];
    const float* eb1 = (const float*)d_in[15];
    const float* ew2 = (const float*)d_in[16];
    const float* eb2 = (const float*)d_in[17];
    const float* cw1 = (const float*)d_in[18];
    const float* cb1 = (const float*)d_in[19];
    const float* cw2 = (const float*)d_in[20];
    const float* nw1 = (const float*)d_in[21];
    const float* nb1 = (const float*)d_in[22];
    const float* nw2 = (const float*)d_in[23];
    const float* nb2 = (const float*)d_in[24];
    float* out = (float*)d_out;

    const int* rowi = edge_index;
    const int* coli = edge_index + Ee;

    const int SMEM_EDGE = SMEM_EDGE_WORDS * 4;
    const int SMEM_HF   = 64 * 64 * 4;

    cudaFuncSetAttribute(edge_mma_kernel, cudaFuncAttributeMaxDynamicSharedMemorySize, SMEM_EDGE);
    cudaFuncSetAttribute(node_mma_kernel, cudaFuncAttributeMaxDynamicSharedMemorySize, SMEM_EDGE);

    init_kernel<<<1 + NB_AGG + 4, 256>>>(t, time_w1, time_b1, time_w2, time_b2,
                                         edge_emb_w, edge_emb_b, ew1, eb1);
    emb_kernel<<<NB_HF + NB_CX, 256, SMEM_HF>>>(h, node_emb_w, node_emb_b, x);

    for (int l = 0; l < 4; l++) {
        int sr = l & 1;
        int sw = 1 - sr;
        edge_mma_kernel<<<EDGE_GRID, EDGE_THREADS, SMEM_EDGE>>>(
            rowi, coli, edge_attr, ew1 + (size_t)l * 385 * Hh,
            ew2 + (size_t)l * Hh * Hh, eb2 + l * Hh,
            cw1 + (size_t)l * Hh * Hh, cb1 + l * Hh,
            cw2 + (size_t)l * Hh,
            l);
        node_mma_kernel<<<EDGE_GRID, EDGE_THREADS, SMEM_EDGE>>>(
            mask,
            nw1 + (size_t)l * 256 * Hh, nb1 + l * Hh,
            nw2 + (size_t)l * Hh * Hh,  nb2 + l * Hh,
            sr, sw);
    }

    final_kernel<<<(Nn + 255) / 256, 256>>>(x, mask, out);
}

// round 17
// speedup vs baseline: 1.1299x; 1.0094x over previous
#include <cuda_runtime.h>
#include <cuda_bf16.h>
#include <math.h>
#include <stdint.h>

#define Nn 10000
#define Ee 320000
#define Hh 128
#define EPSf 1e-8f
#define NT64 5000
#define EDGE_GRID 148
#define EDGE_THREADS 512
#define NPQT 157           // 64-node tiles

// ---------------- scratch ----------------------------------------------------
__device__ float g_temb[Hh];
__device__ float g_hfeat[2][Nn * Hh];
__device__ float g_x[2][Nn * 3];
__device__ float g_P[Nn * Hh];
__device__ float g_Q[Nn * Hh];
__device__ float g_CW[4 * 16 * Hh];
__device__ float g_b1eff[4 * Hh];
__device__ float g_aggmsg[Nn * Hh];
__device__ float g_aggtrans[Nn * 3];
__device__ int g_bar_cnt = 0;
__device__ volatile int g_bar_epoch = 0;

__device__ __forceinline__ float siluf(float x) { return x / (1.0f + __expf(-x)); }

__device__ __forceinline__ void mma16(float* d, const uint32_t* a, uint32_t b0, uint32_t b1) {
    asm volatile("mma.sync.aligned.m16n8k16.row.col.f32.bf16.bf16.f32 "
        "{%0,%1,%2,%3}, {%4,%5,%6,%7}, {%8,%9}, {%0,%1,%2,%3};"
        : "+f"(d[0]), "+f"(d[1]), "+f"(d[2]), "+f"(d[3])
        : "r"(a[0]), "r"(a[1]), "r"(a[2]), "r"(a[3]), "r"(b0), "r"(b1));
}

__device__ __forceinline__ void ldm4(uint32_t* r, uint32_t addr) {
    asm volatile("ldmatrix.sync.aligned.m8n8.x4.shared.b16 {%0,%1,%2,%3}, [%4];"
        : "=r"(r[0]), "=r"(r[1]), "=r"(r[2]), "=r"(r[3]) : "r"(addr));
}

__device__ __forceinline__ uint32_t smem_u32(const void* p) {
    uint32_t a;
    asm("{ .reg .u64 t; cvta.to.shared.u64 t, %1; cvt.u32.u64 %0, t; }" : "=r"(a) : "l"(p));
    return a;
}

__device__ __forceinline__ void split2(float x0, float x1, uint32_t& hi, uint32_t& lo) {
    __nv_bfloat162 h = __floats2bfloat162_rn(x0, x1);
    float h0 = __bfloat162float(__low2bfloat16(h));
    float h1 = __bfloat162float(__high2bfloat16(h));
    __nv_bfloat162 l = __floats2bfloat162_rn(x0 - h0, x1 - h1);
    hi = *(uint32_t*)&h;
    lo = *(uint32_t*)&l;
}

__device__ __forceinline__ void bar_sync(int id, int cnt) {
    asm volatile("bar.sync %0, %1;" :: "r"(id), "r"(cnt) : "memory");
}

// epoch-based device-wide barrier (all CTAs resident) — used only in edge PQ
__device__ __forceinline__ void global_bar() {
    __syncthreads();
    if (threadIdx.x == 0) {
        int e = g_bar_epoch;
        __threadfence();
        int v = atomicAdd(&g_bar_cnt, 1);
        if (v == (int)gridDim.x - 1) {
            g_bar_cnt = 0;
            __threadfence();
            g_bar_epoch = e + 1;
        } else {
            while (g_bar_epoch == e) __nanosleep(64);
        }
    }
    __syncthreads();
    __threadfence();
}

// ================= init = temb | zero agg | setup x4 =========================
#define NB_AGG 5118
__global__ void __launch_bounds__(256, 1) init_kernel(
    const float* __restrict__ t,
    const float* __restrict__ w1, const float* __restrict__ b1,
    const float* __restrict__ w2, const float* __restrict__ b2,
    const float* __restrict__ eew, const float* __restrict__ eeb,
    const float* __restrict__ ew1, const float* __restrict__ eb1) {
    int b = blockIdx.x, tid = threadIdx.x;
    if (b == 0) {
        __shared__ float sh[Hh];
        float tv = t[0];
        if (tid < Hh) sh[tid] = siluf(tv * w1[tid] + b1[tid]);
        __syncthreads();
        if (tid < Hh) {
            float acc = b2[tid];
            #pragma unroll 4
            for (int k = 0; k < Hh; k++) acc = fmaf(sh[k], w2[k * Hh + tid], acc);
            g_temb[tid] = acc;
        }
    } else if (b <= NB_AGG) {
        int i = (b - 1) * 256 + tid;
        if (i < Nn * Hh) g_aggmsg[i] = 0.f;
        else if (i < Nn * Hh + Nn * 3) g_aggtrans[i - Nn * Hh] = 0.f;
    } else {
        int L = b - NB_AGG - 1;
        const float* W1 = ew1 + (size_t)L * 385 * Hh;
        const float* B1 = eb1 + L * Hh;
        float* CW = g_CW + L * 16 * Hh;
        float* be = g_b1eff + L * Hh;
        for (int o = tid; o < 16 * Hh; o += 256) {
            int i = o >> 7, j = o & 127;
            float acc = 0.f;
            #pragma unroll 4
            for (int k = 0; k < Hh; k++)
                acc = fmaf(eew[i * Hh + k], W1[(257 + k) * Hh + j], acc);
            CW[o] = acc;
        }
        if (tid < Hh) {
            float acc = B1[tid];
            #pragma unroll 4
            for (int k = 0; k < Hh; k++)
                acc = fmaf(eeb[k], W1[(257 + k) * Hh + tid], acc);
            be[tid] = acc;
        }
    }
}

// ====== emb: hfeat(h@W+b+temb) | copyx =======================================
#define NB_HF 157
#define NB_CX 118
__global__ void __launch_bounds__(256, 1) emb_kernel(
    const float* __restrict__ h, const float* __restrict__ W, const float* __restrict__ B,
    const float* __restrict__ x) {
    int b = blockIdx.x, tid = threadIdx.x;
    if (b < NB_HF) {
        extern __shared__ float sIn[];
        int n0 = b * 64;
        for (int idx = tid; idx < 64 * 64; idx += 256) {
            int i = idx >> 6, k = idx & 63;
            int node = n0 + i;
            sIn[idx] = (node < Nn) ? h[node * 64 + k] : 0.f;
        }
        __syncthreads();
        int jc = tid & 31, wp = tid >> 5;
        float acc[8][4];
        #pragma unroll
        for (int r = 0; r < 8; r++) { acc[r][0]=acc[r][1]=acc[r][2]=acc[r][3]=0.f; }
        const float4* Wv = (const float4*)W;
        for (int k = 0; k < 64; k++) {
            float4 w = Wv[k * 32 + jc];
            #pragma unroll
            for (int r = 0; r < 8; r++) {
                float a = sIn[(wp * 8 + r) * 64 + k];
                acc[r][0]=fmaf(a,w.x,acc[r][0]); acc[r][1]=fmaf(a,w.y,acc[r][1]);
                acc[r][2]=fmaf(a,w.z,acc[r][2]); acc[r][3]=fmaf(a,w.w,acc[r][3]);
            }
        }
        float4 bv = ((const float4*)B)[jc];
        float4 tv = ((const float4*)g_temb)[jc];
        #pragma unroll
        for (int r = 0; r < 8; r++) {
            int node = n0 + wp * 8 + r;
            if (node < Nn) {
                float4 o;
                o.x = acc[r][0]+bv.x+tv.x; o.y = acc[r][1]+bv.y+tv.y;
                o.z = acc[r][2]+bv.z+tv.z; o.w = acc[r][3]+bv.w+tv.w;
                ((float4*)(g_hfeat[0] + node * Hh))[jc] = o;
            }
        }
    } else {
        int i = (b - NB_HF) * 256 + tid;
        if (i < Nn * 3) g_x[0][i] = x[i];
    }
}

// ============ edge kernel: PQ mma pre-phase + dual-pipeline edge tiles =======
#define O_W2H  0
#define O_W2L  8704
#define O_C1H  17408
#define O_C1L  26112
#define O_A    34816
#define O_EA   52224
#define O_CW   54272
#define O_WD   56320
#define O_B1   56448
#define O_B2   56576
#define O_CB   56704
#define O_C2   56832
#define O_GEO  56960
#define SMEM_EDGE_WORDS 57984

__global__ void __launch_bounds__(EDGE_THREADS, 1) edge_mma_kernel(
    const int* __restrict__ rowi, const int* __restrict__ coli,
    const float* __restrict__ ea,
    const float* __restrict__ W1,
    const float* __restrict__ W2g, const float* __restrict__ B2,
    const float* __restrict__ C1g, const float* __restrict__ CB,
    const float* __restrict__ C2, int l) {
    extern __shared__ float F[];
    uint32_t* U = (uint32_t*)F;
    uint32_t* sW2H = U + O_W2H;
    uint32_t* sW2L = U + O_W2L;
    uint32_t* sC1H = U + O_C1H;
    uint32_t* sC1L = U + O_C1L;
    float* sCW = F + O_CW;
    float* sWd = F + O_WD;
    float* sB1 = F + O_B1;
    float* sB2 = F + O_B2;
    float* sCB = F + O_CB;
    float* sC2 = F + O_C2;

    int tid = threadIdx.x;
    int lane = tid & 31, w = tid >> 5;
    int sel = l & 1;

    const float* xc = g_x[sel];
    const float* hf = g_hfeat[sel];

    int grp = w >> 3;
    int gw = w & 7;
    int gtid = tid & 255;
    int barid = 1 + grp;
    int mi = gw & 1, ni = gw >> 1;
    int g = lane >> 2, tg = lane & 3;

    uint32_t* AH = U + O_A + grp * 8704;
    uint32_t* AL = AH + 4352;
    float* sEA  = F + O_EA + grp * 1024;
    float* GEO  = F + O_GEO + grp * 512;
    int*   sRow = (int*)GEO;
    int*   sCol = (int*)(GEO + 64);
    float* sD2v = GEO + 128;
    float* sDist= GEO + 192;
    float* sPart= GEO + 256;
    float* sDiff= GEO + 320;

    uint32_t uAH = smem_u32(AH), uAL = smem_u32(AL);
    uint32_t uW2H = smem_u32(sW2H), uW2L = smem_u32(sW2L);
    uint32_t uC1H = smem_u32(sC1H), uC1L = smem_u32(sC1L);
    int l15 = lane & 15;
    uint32_t aoff0 = (uint32_t)(((mi * 32 + l15) * 68 + (lane >> 4) * 4) * 4);
    uint32_t aoff1 = aoff0 + 16 * 68 * 4;
    int bj = (lane >> 4) & 1, bg = (lane >> 3) & 1, b8 = lane & 7;
    uint32_t boff0 = (uint32_t)(((ni * 32 + bj * 8 + b8) * 68 + bg * 4) * 4);
    uint32_t boff1 = boff0 + 16 * 68 * 4;

    int tt = blockIdx.x * 2 + grp;

    // ---- PQ pre-phase: stage A = hf rows FIRST (independent of weights) ----
    if (tt < NPQT) {
        int n0 = tt * 64;
        int jc = lane;
        #pragma unroll
        for (int r = 0; r < 8; r++) {
            int row = gw * 8 + r;
            int node = n0 + row;
            float4 hv = (node < Nn) ? ((const float4*)(hf + (size_t)node * Hh))[jc]
                                    : make_float4(0.f, 0.f, 0.f, 0.f);
            uint32_t h0, l0, h1p, l1;
            split2(hv.x, hv.y, h0, l0);
            split2(hv.z, hv.w, h1p, l1);
            *(uint2*)(AH + row * 68 + 2 * jc) = make_uint2(h0, h1p);
            *(uint2*)(AL + row * 68 + 2 * jc) = make_uint2(l0, l1);
        }
    }
    // stage W1a / W1b
    for (int idx = tid; idx < 64 * 128; idx += EDGE_THREADS) {
        int kp = idx >> 7, n = idx & 127;
        uint32_t hi, lo;
        split2(W1[(2 * kp) * Hh + n], W1[(2 * kp + 1) * Hh + n], hi, lo);
        sW2H[n * 68 + kp] = hi;
        sW2L[n * 68 + kp] = lo;
        split2(W1[(128 + 2 * kp) * Hh + n], W1[(128 + 2 * kp + 1) * Hh + n], hi, lo);
        sC1H[n * 68 + kp] = hi;
        sC1L[n * 68 + kp] = lo;
    }
    __syncthreads();

    if (tt < NPQT) {
        int n0 = tt * 64;
        float d[2][4][4];
        #pragma unroll
        for (int pass = 0; pass < 2; pass++) {
            uint32_t uBH = pass ? uC1H : uW2H;
            uint32_t uBL = pass ? uC1L : uW2L;
            float* dstG = pass ? g_Q : g_P;
            #pragma unroll
            for (int mt = 0; mt < 2; mt++)
                #pragma unroll
                for (int j = 0; j < 4; j++)
                    d[mt][j][0] = d[mt][j][1] = d[mt][j][2] = d[mt][j][3] = 0.f;
            #pragma unroll
            for (int ks = 0; ks < 8; ks++) {
                uint32_t koff = (uint32_t)(ks * 32);
                uint32_t ah0[4], ah1[4], al0[4], al1[4], bh[8], bl[8];
                ldm4(ah0, uAH + aoff0 + koff);
                ldm4(ah1, uAH + aoff1 + koff);
                ldm4(al0, uAL + aoff0 + koff);
                ldm4(al1, uAL + aoff1 + koff);
                ldm4(bh,     uBH + boff0 + koff);
                ldm4(bh + 4, uBH + boff1 + koff);
                ldm4(bl,     uBL + boff0 + koff);
                ldm4(bl + 4, uBL + boff1 + koff);
                #pragma unroll
                for (int j = 0; j < 4; j++) {
                    uint32_t b0h = bh[j*2], b1h = bh[j*2+1];
                    uint32_t b0l = bl[j*2], b1l = bl[j*2+1];
                    mma16(d[0][j], ah0, b0h, b1h);
                    mma16(d[1][j], ah1, b0h, b1h);
                    mma16(d[0][j], ah0, b0l, b1l);
                    mma16(d[1][j], ah1, b0l, b1l);
                    mma16(d[0][j], al0, b0h, b1h);
                    mma16(d[1][j], al1, b0h, b1h);
                }
            }
            #pragma unroll
            for (int mt = 0; mt < 2; mt++) {
                int row0 = mi * 32 + mt * 16 + g;
                int row1 = row0 + 8;
                int nd0 = n0 + row0, nd1 = n0 + row1;
                #pragma unroll
                for (int j = 0; j < 4; j++) {
                    int c = ni * 32 + j * 8 + 2 * tg;
                    if (nd0 < Nn)
                        *(float2*)(dstG + (size_t)nd0 * Hh + c) = make_float2(d[mt][j][0], d[mt][j][1]);
                    if (nd1 < Nn)
                        *(float2*)(dstG + (size_t)nd1 * Hh + c) = make_float2(d[mt][j][2], d[mt][j][3]);
                }
            }
        }
    }

    global_bar();

    // ---- stage real edge weights ----
    for (int idx = tid; idx < 64 * 128; idx += EDGE_THREADS) {
        int kp = idx >> 7, n = idx & 127;
        uint32_t hi, lo;
        split2(W2g[(2 * kp) * 128 + n], W2g[(2 * kp + 1) * 128 + n], hi, lo);
        sW2H[n * 68 + kp] = hi;
        sW2L[n * 68 + kp] = lo;
        split2(C1g[(2 * kp) * 128 + n], C1g[(2 * kp + 1) * 128 + n], hi, lo);
        sC1H[n * 68 + kp] = hi;
        sC1L[n * 68 + kp] = lo;
    }
    {
        const float* CWl = g_CW + l * 16 * Hh;
        for (int idx = tid; idx < 16 * Hh; idx += EDGE_THREADS) sCW[idx] = CWl[idx];
    }
    if (tid < Hh) {
        sWd[tid] = W1[256 * Hh + tid];
        sB1[tid] = g_b1eff[l * Hh + tid];
        sB2[tid] = B2[tid];
        sCB[tid] = CB[tid];
        sC2[tid] = C2[tid];
    }
    __syncthreads();

    int stride = gridDim.x * 2;
    int tile0 = blockIdx.x * 2 + grp;

    int pf_r = 0, pf_c = 0;
    float4 pf_ea = make_float4(0.f, 0.f, 0.f, 0.f);
    if (tile0 < NT64) {
        int e0 = tile0 * 64;
        if (gtid < 64) { pf_r = rowi[e0 + gtid]; pf_c = coli[e0 + gtid]; }
        pf_ea = ((const float4*)(ea + (size_t)(e0 + (gtid >> 2)) * 16))[gtid & 3];
    }

    for (int tile = tile0; tile < NT64; tile += stride) {
        if (gtid < 64) {
            int r = pf_r, c = pf_c;
            sRow[gtid] = r; sCol[gtid] = c;
            float dx = xc[r*3+0] - xc[c*3+0];
            float dy = xc[r*3+1] - xc[c*3+1];
            float dz = xc[r*3+2] - xc[c*3+2];
            float d2 = dx*dx + dy*dy + dz*dz;
            sDiff[gtid*3+0] = dx; sDiff[gtid*3+1] = dy; sDiff[gtid*3+2] = dz;
            sD2v[gtid] = d2;
            sDist[gtid] = sqrtf(d2 + EPSf);
            sPart[gtid] = 0.f;
        }
        {
            int e = gtid >> 2, q = gtid & 3;
            float* dst = sEA + e * 16 + q * 4;
            dst[0] = pf_ea.x; dst[1] = pf_ea.y; dst[2] = pf_ea.z; dst[3] = pf_ea.w;
        }
        bar_sync(barid, 256);

        {
            int tn = tile + stride;
            if (tn < NT64) {
                int e0n = tn * 64;
                if (gtid < 64) { pf_r = rowi[e0n + gtid]; pf_c = coli[e0n + gtid]; }
                pf_ea = ((const float4*)(ea + (size_t)(e0n + (gtid >> 2)) * 16))[gtid & 3];
            }
        }

        {
            int jc = lane;
            float acc[8][4];
            float4 wd = ((const float4*)sWd)[jc];
            float4 b1 = ((const float4*)sB1)[jc];
            #pragma unroll
            for (int r = 0; r < 8; r++) {
                int e = gw * 8 + r;
                int rw = sRow[e], cl = sCol[e];
                float d2 = sD2v[e];
                float4 pp = ((const float4*)(g_P + (size_t)rw * Hh))[jc];
                float4 qq = ((const float4*)(g_Q + (size_t)cl * Hh))[jc];
                acc[r][0] = pp.x + qq.x + fmaf(d2, wd.x, b1.x);
                acc[r][1] = pp.y + qq.y + fmaf(d2, wd.y, b1.y);
                acc[r][2] = pp.z + qq.z + fmaf(d2, wd.z, b1.z);
                acc[r][3] = pp.w + qq.w + fmaf(d2, wd.w, b1.w);
            }
            const float4* CW4 = (const float4*)sCW;
            #pragma unroll
            for (int k = 0; k < 16; k++) {
                float4 cw = CW4[k * 32 + jc];
                #pragma unroll
                for (int r = 0; r < 8; r++) {
                    float a = sEA[(gw * 8 + r) * 16 + k];
                    acc[r][0] = fmaf(a, cw.x, acc[r][0]);
                    acc[r][1] = fmaf(a, cw.y, acc[r][1]);
                    acc[r][2] = fmaf(a, cw.z, acc[r][2]);
                    acc[r][3] = fmaf(a, cw.w, acc[r][3]);
                }
            }
            #pragma unroll
            for (int r = 0; r < 8; r++) {
                int e = gw * 8 + r;
                float s0 = siluf(acc[r][0]), s1 = siluf(acc[r][1]);
                float s2 = siluf(acc[r][2]), s3 = siluf(acc[r][3]);
                uint32_t h0, l0, h1p, l1;
                split2(s0, s1, h0, l0);
                split2(s2, s3, h1p, l1);
                *(uint2*)(AH + e * 68 + 2 * jc) = make_uint2(h0, h1p);
                *(uint2*)(AL + e * 68 + 2 * jc) = make_uint2(l0, l1);
            }
        }
        bar_sync(barid, 256);

        float d[2][4][4];

        #pragma unroll
        for (int mt = 0; mt < 2; mt++)
            #pragma unroll
            for (int j = 0; j < 4; j++)
                d[mt][j][0] = d[mt][j][1] = d[mt][j][2] = d[mt][j][3] = 0.f;
        #pragma unroll
        for (int ks = 0; ks < 8; ks++) {
            uint32_t koff = (uint32_t)(ks * 32);
            uint32_t ah0[4], ah1[4], al0[4], al1[4], bh[8], bl[8];
            ldm4(ah0, uAH + aoff0 + koff);
            ldm4(ah1, uAH + aoff1 + koff);
            ldm4(al0, uAL + aoff0 + koff);
            ldm4(al1, uAL + aoff1 + koff);
            ldm4(bh,     uW2H + boff0 + koff);
            ldm4(bh + 4, uW2H + boff1 + koff);
            ldm4(bl,     uW2L + boff0 + koff);
            ldm4(bl + 4, uW2L + boff1 + koff);
            #pragma unroll
            for (int j = 0; j < 4; j++) {
                uint32_t b0h = bh[j*2], b1h = bh[j*2+1];
                uint32_t b0l = bl[j*2], b1l = bl[j*2+1];
                mma16(d[0][j], ah0, b0h, b1h);
                mma16(d[1][j], ah1, b0h, b1h);
                mma16(d[0][j], ah0, b0l, b1l);
                mma16(d[1][j], ah1, b0l, b1l);
                mma16(d[0][j], al0, b0h, b1h);
                mma16(d[1][j], al1, b0h, b1h);
            }
        }
        bar_sync(barid, 256);

        #pragma unroll
        for (int mt = 0; mt < 2; mt++) {
            int er0 = mi * 32 + mt * 16 + g;
            int er1 = er0 + 8;
            int rw0 = sRow[er0], rw1 = sRow[er1];
            #pragma unroll
            for (int j = 0; j < 4; j++) {
                int c = ni * 32 + j * 8 + 2 * tg;
                float m00 = siluf(d[mt][j][0] + sB2[c]);
                float m01 = siluf(d[mt][j][1] + sB2[c + 1]);
                float m10 = siluf(d[mt][j][2] + sB2[c]);
                float m11 = siluf(d[mt][j][3] + sB2[c + 1]);
                asm volatile("red.global.add.v2.f32 [%0], {%1,%2};"
                             :: "l"(g_aggmsg + (size_t)rw0 * Hh + c), "f"(m00), "f"(m01) : "memory");
                asm volatile("red.global.add.v2.f32 [%0], {%1,%2};"
                             :: "l"(g_aggmsg + (size_t)rw1 * Hh + c), "f"(m10), "f"(m11) : "memory");
                uint32_t hi, lo;
                split2(m00, m01, hi, lo);
                AH[er0 * 68 + (c >> 1)] = hi;
                AL[er0 * 68 + (c >> 1)] = lo;
                split2(m10, m11, hi, lo);
                AH[er1 * 68 + (c >> 1)] = hi;
                AL[er1 * 68 + (c >> 1)] = lo;
            }
        }
        bar_sync(barid, 256);

        #pragma unroll
        for (int mt = 0; mt < 2; mt++)
            #pragma unroll
            for (int j = 0; j < 4; j++)
                d[mt][j][0] = d[mt][j][1] = d[mt][j][2] = d[mt][j][3] = 0.f;
        #pragma unroll
        for (int ks = 0; ks < 8; ks++) {
            uint32_t koff = (uint32_t)(ks * 32);
            uint32_t ah0[4], ah1[4], al0[4], al1[4], bh[8], bl[8];
            ldm4(ah0, uAH + aoff0 + koff);
            ldm4(ah1, uAH + aoff1 + koff);
            ldm4(al0, uAL + aoff0 + koff);
            ldm4(al1, uAL + aoff1 + koff);
            ldm4(bh,     uC1H + boff0 + koff);
            ldm4(bh + 4, uC1H + boff1 + koff);
            ldm4(bl,     uC1L + boff0 + koff);
            ldm4(bl + 4, uC1L + boff1 + koff);
            #pragma unroll
            for (int j = 0; j < 4; j++) {
                uint32_t b0h = bh[j*2], b1h = bh[j*2+1];
                uint32_t b0l = bl[j*2], b1l = bl[j*2+1];
                mma16(d[0][j], ah0, b0h, b1h);
                mma16(d[1][j], ah1, b0h, b1h);
                mma16(d[0][j], ah0, b0l, b1l);
                mma16(d[1][j], ah1, b0l, b1l);
                mma16(d[0][j], al0, b0h, b1h);
                mma16(d[1][j], al1, b0h, b1h);
            }
        }

        {
            float prt[2][2];
            prt[0][0] = prt[0][1] = prt[1][0] = prt[1][1] = 0.f;
            #pragma unroll
            for (int mt = 0; mt < 2; mt++) {
                #pragma unroll
                for (int j = 0; j < 4; j++) {
                    int c = ni * 32 + j * 8 + 2 * tg;
                    float c2a = sC2[c], c2b = sC2[c + 1];
                    float u00 = siluf(d[mt][j][0] + sCB[c]);
                    float u01 = siluf(d[mt][j][1] + sCB[c + 1]);
                    float u10 = siluf(d[mt][j][2] + sCB[c]);
                    float u11 = siluf(d[mt][j][3] + sCB[c + 1]);
                    prt[mt][0] += u00 * c2a + u01 * c2b;
                    prt[mt][1] += u10 * c2a + u11 * c2b;
                }
            }
            #pragma unroll
            for (int mt = 0; mt < 2; mt++) {
                #pragma unroll
                for (int rh = 0; rh < 2; rh++) {
                    float pv = prt[mt][rh];
                    pv += __shfl_xor_sync(0xffffffffu, pv, 1);
                    pv += __shfl_xor_sync(0xffffffffu, pv, 2);
                    if (tg == 0)
                        atomicAdd(&sPart[mi * 32 + mt * 16 + rh * 8 + g], pv);
                }
            }
        }
        bar_sync(barid, 256);

        if (gtid < 64) {
            float wsc = tanhf(sPart[gtid]);
            float s = wsc / (sDist[gtid] + EPSf);
            int rw = sRow[gtid];
            atomicAdd(&g_aggtrans[rw * 3 + 0], sDiff[gtid * 3 + 0] * s);
            atomicAdd(&g_aggtrans[rw * 3 + 1], sDiff[gtid * 3 + 1] * s);
            atomicAdd(&g_aggtrans[rw * 3 + 2], sDiff[gtid * 3 + 2] * s);
        }
        bar_sync(barid, 256);
    }
}

// ============ node mma kernel (CTA-local, latency-overlapped) ================
__global__ void __launch_bounds__(EDGE_THREADS, 1) node_mma_kernel(
    const float* __restrict__ mask,
    const float* __restrict__ N1w, const float* __restrict__ NB1,
    const float* __restrict__ N2w, const float* __restrict__ NB2,
    int selr, int selw) {
    if (blockIdx.x * 2 >= NPQT) return;   // idle CTAs exit early
    extern __shared__ float F[];
    uint32_t* U = (uint32_t*)F;
    uint32_t* sBaH = U + O_W2H;   // N1a then N2
    uint32_t* sBaL = U + O_W2L;
    uint32_t* sBbH = U + O_C1H;   // N1b
    uint32_t* sBbL = U + O_C1L;
    float* sB1 = F + O_B1;
    float* sB2 = F + O_B2;

    const float* hc = g_hfeat[selr];
    float* hn = g_hfeat[selw];

    int tid = threadIdx.x;
    int lane = tid & 31, w = tid >> 5;
    int grp = w >> 3;
    int gw = w & 7;
    int gtid = tid & 255;
    int barid = 1 + grp;
    int mi = gw & 1, ni = gw >> 1;
    int g = lane >> 2, tg = lane & 3;

    uint32_t* AH = U + O_A + grp * 8704;
    uint32_t* AL = AH + 4352;
    uint32_t uAH = smem_u32(AH), uAL = smem_u32(AL);
    uint32_t uBaH = smem_u32(sBaH), uBaL = smem_u32(sBaL);
    uint32_t uBbH = smem_u32(sBbH), uBbL = smem_u32(sBbL);
    int l15 = lane & 15;
    uint32_t aoff0 = (uint32_t)(((mi * 32 + l15) * 68 + (lane >> 4) * 4) * 4);
    uint32_t aoff1 = aoff0 + 16 * 68 * 4;
    int bj = (lane >> 4) & 1, bg = (lane >> 3) & 1, b8 = lane & 7;
    uint32_t boff0 = (uint32_t)(((ni * 32 + bj * 8 + b8) * 68 + bg * 4) * 4);
    uint32_t boff1 = boff0 + 16 * 68 * 4;

    int tt = blockIdx.x * 2 + grp;
    bool act = tt < NPQT;
    int n0 = tt * 64;

    // ---- stage h -> A first (independent of weights; overlaps staging) ----
    if (act) {
        int jc = lane;
        #pragma unroll
        for (int r = 0; r < 8; r++) {
            int row = gw * 8 + r;
            int node = n0 + row;
            float4 hv = (node < Nn) ? ((const float4*)(hc + (size_t)node * Hh))[jc]
                                    : make_float4(0.f, 0.f, 0.f, 0.f);
            uint32_t h0, l0, h1p, l1;
            split2(hv.x, hv.y, h0, l0);
            split2(hv.z, hv.w, h1p, l1);
            *(uint2*)(AH + row * 68 + 2 * jc) = make_uint2(h0, h1p);
            *(uint2*)(AL + row * 68 + 2 * jc) = make_uint2(l0, l1);
        }
    }
    // ---- stage N1a and N1b ----
    for (int idx = tid; idx < 64 * 128; idx += EDGE_THREADS) {
        int kp = idx >> 7, n = idx & 127;
        uint32_t hi, lo;
        split2(N1w[(2 * kp) * Hh + n], N1w[(2 * kp + 1) * Hh + n], hi, lo);
        sBaH[n * 68 + kp] = hi;
        sBaL[n * 68 + kp] = lo;
        split2(N1w[(128 + 2 * kp) * Hh + n], N1w[(128 + 2 * kp + 1) * Hh + n], hi, lo);
        sBbH[n * 68 + kp] = hi;
        sBbL[n * 68 + kp] = lo;
    }
    if (tid < Hh) {
        sB1[tid] = NB1[tid];
        sB2[tid] = NB2[tid];
    }
    __syncthreads();

    float d[2][4][4];
    #pragma unroll
    for (int mt = 0; mt < 2; mt++)
        #pragma unroll
        for (int j = 0; j < 4; j++)
            d[mt][j][0] = d[mt][j][1] = d[mt][j][2] = d[mt][j][3] = 0.f;

    // ---- pass A mma: h @ N1a ----
    if (act) {
        #pragma unroll
        for (int ks = 0; ks < 8; ks++) {
            uint32_t koff = (uint32_t)(ks * 32);
            uint32_t ah0[4], ah1[4], al0[4], al1[4], bh[8], bl[8];
            ldm4(ah0, uAH + aoff0 + koff);
            ldm4(ah1, uAH + aoff1 + koff);
            ldm4(al0, uAL + aoff0 + koff);
            ldm4(al1, uAL + aoff1 + koff);
            ldm4(bh,     uBaH + boff0 + koff);
            ldm4(bh + 4, uBaH + boff1 + koff);
            ldm4(bl,     uBaL + boff0 + koff);
            ldm4(bl + 4, uBaL + boff1 + koff);
            #pragma unroll
            for (int j = 0; j < 4; j++) {
                uint32_t b0h = bh[j*2], b1h = bh[j*2+1];
                uint32_t b0l = bl[j*2], b1l = bl[j*2+1];
                mma16(d[0][j], ah0, b0h, b1h);
                mma16(d[1][j], ah1, b0h, b1h);
                mma16(d[0][j], ah0, b0l, b1l);
                mma16(d[1][j], ah1, b0l, b1l);
                mma16(d[0][j], al0, b0h, b1h);
                mma16(d[1][j], al1, b0h, b1h);
            }
        }
    }

    // ---- prefetch agg into regs (loads complete during barrier wait) ----
    float4 aggr[8];
    if (act) {
        int jc = lane;
        #pragma unroll
        for (int r = 0; r < 8; r++) {
            int row = gw * 8 + r;
            int node = n0 + row;
            aggr[r] = make_float4(0.f, 0.f, 0.f, 0.f);
            if (node < Nn) {
                float4* ap = (float4*)(g_aggmsg + (size_t)node * Hh) + jc;
                aggr[r] = *ap;
                *ap = make_float4(0.f, 0.f, 0.f, 0.f);
            }
        }
    }
    __syncthreads();   // all warps done reading N1a and A

    // ---- issue N2 re-staging now (overlaps pass-B mma below) ----
    for (int idx = tid; idx < 64 * 128; idx += EDGE_THREADS) {
        int kp = idx >> 7, n = idx & 127;
        uint32_t hi, lo;
        split2(N2w[(2 * kp) * Hh + n], N2w[(2 * kp + 1) * Hh + n], hi, lo);
        sBaH[n * 68 + kp] = hi;
        sBaL[n * 68 + kp] = lo;
    }

    // ---- store agg regs -> A (split) ----
    if (act) {
        int jc = lane;
        #pragma unroll
        for (int r = 0; r < 8; r++) {
            int row = gw * 8 + r;
            uint32_t h0, l0, h1p, l1;
            split2(aggr[r].x, aggr[r].y, h0, l0);
            split2(aggr[r].z, aggr[r].w, h1p, l1);
            *(uint2*)(AH + row * 68 + 2 * jc) = make_uint2(h0, h1p);
            *(uint2*)(AL + row * 68 + 2 * jc) = make_uint2(l0, l1);
        }
        bar_sync(barid, 256);

        // ---- pass B mma: agg @ N1b (accumulate; overlaps N2 staging) ----
        #pragma unroll
        for (int ks = 0; ks < 8; ks++) {
            uint32_t koff = (uint32_t)(ks * 32);
            uint32_t ah0[4], ah1[4], al0[4], al1[4], bh[8], bl[8];
            ldm4(ah0, uAH + aoff0 + koff);
            ldm4(ah1, uAH + aoff1 + koff);
            ldm4(al0, uAL + aoff0 + koff);
            ldm4(al1, uAL + aoff1 + koff);
            ldm4(bh,     uBbH + boff0 + koff);
            ldm4(bh + 4, uBbH + boff1 + koff);
            ldm4(bl,     uBbL + boff0 + koff);
            ldm4(bl + 4, uBbL + boff1 + koff);
            #pragma unroll
            for (int j = 0; j < 4; j++) {
                uint32_t b0h = bh[j*2], b1h = bh[j*2+1];
                uint32_t b0l = bl[j*2], b1l = bl[j*2+1];
                mma16(d[0][j], ah0, b0h, b1h);
                mma16(d[1][j], ah1, b0h, b1h);
                mma16(d[0][j], ah0, b0l, b1l);
                mma16(d[1][j], ah1, b0l, b1l);
                mma16(d[0][j], al0, b0h, b1h);
                mma16(d[1][j], al1, b0h, b1h);
            }
        }
        bar_sync(barid, 256);   // all group warps done reading A

        // ---- epilogue: t = silu(d + b1) -> split, kept in group's A ----
        #pragma unroll
        for (int mt = 0; mt < 2; mt++) {
            int er0 = mi * 32 + mt * 16 + g;
            int er1 = er0 + 8;
            #pragma unroll
            for (int j = 0; j < 4; j++) {
                int c = ni * 32 + j * 8 + 2 * tg;
                float t00 = siluf(d[mt][j][0] + sB1[c]);
                float t01 = siluf(d[mt][j][1] + sB1[c + 1]);
                float t10 = siluf(d[mt][j][2] + sB1[c]);
                float t11 = siluf(d[mt][j][3] + sB1[c + 1]);
                uint32_t hi, lo;
                split2(t00, t01, hi, lo);
                AH[er0 * 68 + (c >> 1)] = hi;
                AL[er0 * 68 + (c >> 1)] = lo;
                split2(t10, t11, hi, lo);
                AH[er1 * 68 + (c >> 1)] = hi;
                AL[er1 * 68 + (c >> 1)] = lo;
            }
        }
    }

    __syncthreads();   // N2 staged by all threads + t stored by active groups

    if (act) {
        #pragma unroll
        for (int mt = 0; mt < 2; mt++)
            #pragma unroll
            for (int j = 0; j < 4; j++)
                d[mt][j][0] = d[mt][j][1] = d[mt][j][2] = d[mt][j][3] = 0.f;
        #pragma unroll
        for (int ks = 0; ks < 8; ks++) {
            uint32_t koff = (uint32_t)(ks * 32);
            uint32_t ah0[4], ah1[4], al0[4], al1[4], bh[8], bl[8];
            ldm4(ah0, uAH + aoff0 + koff);
            ldm4(ah1, uAH + aoff1 + koff);
            ldm4(al0, uAL + aoff0 + koff);
            ldm4(al1, uAL + aoff1 + koff);
            ldm4(bh,     uBaH + boff0 + koff);
            ldm4(bh + 4, uBaH + boff1 + koff);
            ldm4(bl,     uBaL + boff0 + koff);
            ldm4(bl + 4, uBaL + boff1 + koff);
            #pragma unroll
            for (int j = 0; j < 4; j++) {
                uint32_t b0h = bh[j*2], b1h = bh[j*2+1];
                uint32_t b0l = bl[j*2], b1l = bl[j*2+1];
                mma16(d[0][j], ah0, b0h, b1h);
                mma16(d[1][j], ah1, b0h, b1h);
                mma16(d[0][j], ah0, b0l, b1l);
                mma16(d[1][j], ah1, b0l, b1l);
                mma16(d[0][j], al0, b0h, b1h);
                mma16(d[1][j], al1, b0h, b1h);
            }
        }

        // epilogue: h_new = hc + d + b2 -> hn
        #pragma unroll
        for (int mt = 0; mt < 2; mt++) {
            int row0 = mi * 32 + mt * 16 + g;
            int row1 = row0 + 8;
            int nd0 = n0 + row0, nd1 = n0 + row1;
            #pragma unroll
            for (int j = 0; j < 4; j++) {
                int c = ni * 32 + j * 8 + 2 * tg;
                if (nd0 < Nn) {
                    float2 hv = *(const float2*)(hc + (size_t)nd0 * Hh + c);
                    *(float2*)(hn + (size_t)nd0 * Hh + c) =
                        make_float2(hv.x + d[mt][j][0] + sB2[c], hv.y + d[mt][j][1] + sB2[c + 1]);
                }
                if (nd1 < Nn) {
                    float2 hv = *(const float2*)(hc + (size_t)nd1 * Hh + c);
                    *(float2*)(hn + (size_t)nd1 * Hh + c) =
                        make_float2(hv.x + d[mt][j][2] + sB2[c], hv.y + d[mt][j][3] + sB2[c + 1]);
                }
            }
        }

        // x update + aggtrans zero
        if (gtid < 64) {
            int node = n0 + gtid;
            if (node < Nn) {
                float mk = mask[node];
                const float* xr = g_x[selr];
                float* xw = g_x[selw];
                float ax = g_aggtrans[node*3+0];
                float ay = g_aggtrans[node*3+1];
                float az = g_aggtrans[node*3+2];
                xw[node*3+0] = xr[node*3+0] + ax * mk;
                xw[node*3+1] = xr[node*3+1] + ay * mk;
                xw[node*3+2] = xr[node*3+2] + az * mk;
                g_aggtrans[node*3+0] = 0.f;
                g_aggtrans[node*3+1] = 0.f;
                g_aggtrans[node*3+2] = 0.f;
            }
        }
    }
}

// ---------------- final ------------------------------------------------------
__global__ void final_kernel(const float* __restrict__ x_in,
                             const float* __restrict__ mask,
                             float* __restrict__ out) {
    int i = blockIdx.x * 256 + threadIdx.x;
    if (i < Nn) {
        float mk = mask[i];
        out[i*3+0] = (g_x[0][i*3+0] - x_in[i*3+0]) * mk;
        out[i*3+1] = (g_x[0][i*3+1] - x_in[i*3+1]) * mk;
        out[i*3+2] = (g_x[0][i*3+2] - x_in[i*3+2]) * mk;
    }
}

// ---------------- launcher ----------------------------------------------------
extern "C" void kernel_launch(void* const* d_in, const int* in_sizes, int n_in,
                              void* d_out, int out_size) {
    const float* h          = (const float*)d_in[0];
    const float* x          = (const float*)d_in[1];
    const int*   edge_index = (const int*)  d_in[2];
    const float* edge_attr  = (const float*)d_in[3];
    const float* t          = (const float*)d_in[4];
    const float* mask       = (const float*)d_in[5];
    const float* time_w1    = (const float*)d_in[6];
    const float* time_b1    = (const float*)d_in[7];
    const float* time_w2    = (const float*)d_in[8];
    const float* time_b2    = (const float*)d_in[9];
    const float* node_emb_w = (const float*)d_in[10];
    const float* node_emb_b = (const float*)d_in[11];
    const float* edge_emb_w = (const float*)d_in[12];
    const float* edge_emb_b = (const float*)d_in[13];
    const float* ew1 = (const float*)d_in[14];
    const float* eb1 = (const float*)d_in[15];
    const float* ew2 = (const float*)d_in[16];
    const float* eb2 = (const float*)d_in[17];
    const float* cw1 = (const float*)d_in[18];
    const float* cb1 = (const float*)d_in[19];
    const float* cw2 = (const float*)d_in[20];
    const float* nw1 = (const float*)d_in[21];
    const float* nb1 = (const float*)d_in[22];
    const float* nw2 = (const float*)d_in[23];
    const float* nb2 = (const float*)d_in[24];
    float* out = (float*)d_out;

    const int* rowi = edge_index;
    const int* coli = edge_index + Ee;

    const int SMEM_EDGE = SMEM_EDGE_WORDS * 4;
    const int SMEM_HF   = 64 * 64 * 4;

    cudaFuncSetAttribute(edge_mma_kernel, cudaFuncAttributeMaxDynamicSharedMemorySize, SMEM_EDGE);
    cudaFuncSetAttribute(node_mma_kernel, cudaFuncAttributeMaxDynamicSharedMemorySize, SMEM_EDGE);

    init_kernel<<<1 + NB_AGG + 4, 256>>>(t, time_w1, time_b1, time_w2, time_b2,
                                         edge_emb_w, edge_emb_b, ew1, eb1);
    emb_kernel<<<NB_HF + NB_CX, 256, SMEM_HF>>>(h, node_emb_w, node_emb_b, x);

    for (int l = 0; l < 4; l++) {
        int sr = l & 1;
        int sw = 1 - sr;
        edge_mma_kernel<<<EDGE_GRID, EDGE_THREADS, SMEM_EDGE>>>(
            rowi, coli, edge_attr, ew1 + (size_t)l * 385 * Hh,
            ew2 + (size_t)l * Hh * Hh, eb2 + l * Hh,
            cw1 + (size_t)l * Hh * Hh, cb1 + l * Hh,
            cw2 + (size_t)l * Hh,
            l);
        node_mma_kernel<<<EDGE_GRID, EDGE_THREADS, SMEM_EDGE>>>(
            mask,
            nw1 + (size_t)l * 256 * Hh, nb1 + l * Hh,
            nw2 + (size_t)l * Hh * Hh,  nb2 + l * Hh,
            sr, sw);
    }

    final_kernel<<<(Nn + 255) / 256, 256>>>(x, mask, out);
}